// round 6
// baseline (speedup 1.0000x reference)
#include <cuda_runtime.h>
#include <cuda_bf16.h>
#include <mma.h>

using namespace nvcuda;
using bf16 = __nv_bfloat16;

#define B_  4
#define C_  512
#define N_  4096
#define G_  32
#define CPG 16           // channels per group = C_/G_

static __device__ __align__(16) bf16  g_hn[(size_t)B_*N_*C_];   // normed x, token-major [b][i][c]; reused for attn output
static __device__ __align__(16) bf16  g_q [(size_t)B_*N_*C_];   // [b][i][c]
static __device__ __align__(16) bf16  g_k [(size_t)B_*N_*C_];
static __device__ __align__(16) bf16  g_v [(size_t)B_*N_*C_];
static __device__ __align__(16) float g_o [(size_t)B_*N_*C_];   // unnormalized attn out (fp32)
static __device__ __align__(16) bf16  g_wt[4][C_*C_];           // transposed bf16 weights: Wt[c][o] = W[o][c]
static __device__ float g_mean[B_*G_];
static __device__ float g_rstd[B_*G_];
static __device__ float g_l[(size_t)B_*N_];                     // softmax denominators

#define RSCALE 0.044194173824159216f   // 1/sqrt(512)

// ---------------------------------------------------------------------------
// K0: weight transpose + bf16 convert.  grid (16,16,4), block (32,8)
// ---------------------------------------------------------------------------
__global__ void prep_weights(const float* __restrict__ wq, const float* __restrict__ wk,
                             const float* __restrict__ wv, const float* __restrict__ wp) {
    __shared__ float t[32][33];
    const float* Wsel[4] = {wq, wk, wv, wp};
    const float* src = Wsel[blockIdx.z];
    int o0 = blockIdx.x * 32, c0 = blockIdx.y * 32;
    int tx = threadIdx.x, ty = threadIdx.y;
#pragma unroll
    for (int k = 0; k < 4; k++)
        t[ty + 8*k][tx] = src[(size_t)(o0 + ty + 8*k) * C_ + c0 + tx];   // t[o_local][c_local]
    __syncthreads();
#pragma unroll
    for (int k = 0; k < 4; k++)
        g_wt[blockIdx.z][(size_t)(c0 + ty + 8*k) * C_ + o0 + tx] = __float2bfloat16(t[tx][ty + 8*k]);
}

// ---------------------------------------------------------------------------
// K1: groupnorm statistics. grid (B*G = 128), block 256
// ---------------------------------------------------------------------------
__global__ void gn_stats(const float* __restrict__ x) {
    int bg = blockIdx.x;
    int b = bg / G_, g = bg % G_;
    const float* base = x + (size_t)b * C_ * N_ + (size_t)g * CPG * N_;
    float s = 0.f, ss = 0.f;
    for (int i = threadIdx.x; i < CPG * N_; i += blockDim.x) {
        float v = base[i];
        s += v; ss += v * v;
    }
#pragma unroll
    for (int o = 16; o; o >>= 1) {
        s  += __shfl_xor_sync(0xffffffffu, s,  o);
        ss += __shfl_xor_sync(0xffffffffu, ss, o);
    }
    __shared__ float rs[8], rss[8];
    int w = threadIdx.x >> 5, lane = threadIdx.x & 31;
    if (lane == 0) { rs[w] = s; rss[w] = ss; }
    __syncthreads();
    if (w == 0) {
        s  = (lane < 8) ? rs[lane]  : 0.f;
        ss = (lane < 8) ? rss[lane] : 0.f;
#pragma unroll
        for (int o = 4; o; o >>= 1) {
            s  += __shfl_xor_sync(0xffffffffu, s,  o);
            ss += __shfl_xor_sync(0xffffffffu, ss, o);
        }
        if (lane == 0) {
            const float M = (float)(CPG * N_);
            float m = s / M;
            float var = ss / M - m * m;
            g_mean[bg] = m;
            g_rstd[bg] = rsqrtf(var + 1e-6f);
        }
    }
}

// ---------------------------------------------------------------------------
// K2: apply groupnorm + transpose to token-major bf16.  grid (128,16,4), block (32,8)
// ---------------------------------------------------------------------------
__global__ void gn_apply(const float* __restrict__ x, const float* __restrict__ gs,
                         const float* __restrict__ gb) {
    __shared__ float t[32][33];
    int b = blockIdx.z;
    int i0 = blockIdx.x * 32, c0 = blockIdx.y * 32;
    int tx = threadIdx.x, ty = threadIdx.y;
    const float* xb = x + (size_t)b * C_ * N_;
#pragma unroll
    for (int k = 0; k < 4; k++)
        t[ty + 8*k][tx] = xb[(size_t)(c0 + ty + 8*k) * N_ + i0 + tx];   // t[c_local][i_local]
    __syncthreads();
#pragma unroll
    for (int k = 0; k < 4; k++) {
        int c = c0 + tx;
        int i = i0 + ty + 8*k;
        int bg = b * G_ + c / CPG;
        float m = g_mean[bg], r = g_rstd[bg];
        float val = (t[tx][ty + 8*k] - m) * r * gs[c] + gb[c];
        g_hn[((size_t)b * N_ + i) * C_ + c] = __float2bfloat16(val);
    }
}

// ---------------------------------------------------------------------------
// Shared GEMM tiling: BM=128, BN=64, BK=32, 8 warps, warp tile 32x32
//   C[i][o] = sum_c A[i][c] * Wt[c][o]
// ---------------------------------------------------------------------------
#define GEMM_SMEM_BYTES (128 * 68 * 4)   // staging dominates (34816 B)

// K3: QKV projection -> bf16 [b][i][o].  grid (32, 8, 12), block 256
__global__ __launch_bounds__(256) void gemm_qkv(const float* __restrict__ bq,
                                                const float* __restrict__ bk,
                                                const float* __restrict__ bv) {
    extern __shared__ char smraw[];
    bf16*  sA = (bf16*)smraw;                     // [128][48]
    bf16*  sB = (bf16*)(smraw + 128 * 48 * 2);    // [32][72]
    float* sC = (float*)smraw;                    // [128][68] (reuses sA/sB)

    int bz = blockIdx.z;
    int b = bz / 3, which = bz % 3;
    const bf16* A  = g_hn + (size_t)b * N_ * C_;
    const bf16* Wt = g_wt[which];
    bf16* outp = (which == 0 ? g_q : which == 1 ? g_k : g_v) + (size_t)b * N_ * C_;
    const float* bias = (which == 0 ? bq : which == 1 ? bk : bv);

    int i0 = blockIdx.x * 128, o0 = blockIdx.y * 64;
    int tid = threadIdx.x, warp = tid >> 5;
    int wr = warp >> 1, wc = warp & 1;

    wmma::fragment<wmma::accumulator, 16, 16, 16, float> acc[2][2];
#pragma unroll
    for (int m = 0; m < 2; m++)
#pragma unroll
        for (int n = 0; n < 2; n++) wmma::fill_fragment(acc[m][n], 0.f);

    for (int k0 = 0; k0 < 16; k0++) {
        int kk = k0 * 32;
#pragma unroll
        for (int t = 0; t < 2; t++) {
            int idx = tid + 256 * t;
            int r = idx >> 2, c8 = idx & 3;
            *(uint4*)(sA + r * 48 + c8 * 8) =
                *(const uint4*)(A + (size_t)(i0 + r) * C_ + kk + c8 * 8);
        }
        {
            int r = tid >> 3, c8 = tid & 7;
            *(uint4*)(sB + r * 72 + c8 * 8) =
                *(const uint4*)(Wt + (size_t)(kk + r) * C_ + o0 + c8 * 8);
        }
        __syncthreads();
#pragma unroll
        for (int ks = 0; ks < 2; ks++) {
            wmma::fragment<wmma::matrix_a, 16, 16, 16, bf16, wmma::row_major> a0, a1;
            wmma::load_matrix_sync(a0, sA + (wr * 32     ) * 48 + ks * 16, 48);
            wmma::load_matrix_sync(a1, sA + (wr * 32 + 16) * 48 + ks * 16, 48);
#pragma unroll
            for (int nn = 0; nn < 2; nn++) {
                wmma::fragment<wmma::matrix_b, 16, 16, 16, bf16, wmma::row_major> bfr;
                wmma::load_matrix_sync(bfr, sB + (ks * 16) * 72 + wc * 32 + nn * 16, 72);
                wmma::mma_sync(acc[0][nn], a0, bfr, acc[0][nn]);
                wmma::mma_sync(acc[1][nn], a1, bfr, acc[1][nn]);
            }
        }
        __syncthreads();
    }
#pragma unroll
    for (int m = 0; m < 2; m++)
#pragma unroll
        for (int nn = 0; nn < 2; nn++)
            wmma::store_matrix_sync(sC + (wr * 32 + m * 16) * 68 + wc * 32 + nn * 16,
                                    acc[m][nn], 68, wmma::mem_row_major);
    __syncthreads();
    for (int idx = tid; idx < 128 * 64; idx += 256) {
        int r = idx >> 6, cl = idx & 63;
        outp[(size_t)(i0 + r) * C_ + o0 + cl] =
            __float2bfloat16(sC[r * 68 + cl] + bias[o0 + cl]);
    }
}

// K6: proj GEMM + bias + residual, transposed store into d_out. grid (32, 8, 4)
__global__ __launch_bounds__(256) void gemm_proj(const float* __restrict__ x,
                                                 const float* __restrict__ bp,
                                                 float* __restrict__ out) {
    extern __shared__ char smraw[];
    bf16*  sA = (bf16*)smraw;
    bf16*  sB = (bf16*)(smraw + 128 * 48 * 2);
    float* sC = (float*)smraw;

    int b = blockIdx.z;
    const bf16* A  = g_hn + (size_t)b * N_ * C_;   // g_hn reused: holds normalized attn out (bf16)
    const bf16* Wt = g_wt[3];

    int i0 = blockIdx.x * 128, o0 = blockIdx.y * 64;
    int tid = threadIdx.x, warp = tid >> 5;
    int wr = warp >> 1, wc = warp & 1;

    wmma::fragment<wmma::accumulator, 16, 16, 16, float> acc[2][2];
#pragma unroll
    for (int m = 0; m < 2; m++)
#pragma unroll
        for (int n = 0; n < 2; n++) wmma::fill_fragment(acc[m][n], 0.f);

    for (int k0 = 0; k0 < 16; k0++) {
        int kk = k0 * 32;
#pragma unroll
        for (int t = 0; t < 2; t++) {
            int idx = tid + 256 * t;
            int r = idx >> 2, c8 = idx & 3;
            *(uint4*)(sA + r * 48 + c8 * 8) =
                *(const uint4*)(A + (size_t)(i0 + r) * C_ + kk + c8 * 8);
        }
        {
            int r = tid >> 3, c8 = tid & 7;
            *(uint4*)(sB + r * 72 + c8 * 8) =
                *(const uint4*)(Wt + (size_t)(kk + r) * C_ + o0 + c8 * 8);
        }
        __syncthreads();
#pragma unroll
        for (int ks = 0; ks < 2; ks++) {
            wmma::fragment<wmma::matrix_a, 16, 16, 16, bf16, wmma::row_major> a0, a1;
            wmma::load_matrix_sync(a0, sA + (wr * 32     ) * 48 + ks * 16, 48);
            wmma::load_matrix_sync(a1, sA + (wr * 32 + 16) * 48 + ks * 16, 48);
#pragma unroll
            for (int nn = 0; nn < 2; nn++) {
                wmma::fragment<wmma::matrix_b, 16, 16, 16, bf16, wmma::row_major> bfr;
                wmma::load_matrix_sync(bfr, sB + (ks * 16) * 72 + wc * 32 + nn * 16, 72);
                wmma::mma_sync(acc[0][nn], a0, bfr, acc[0][nn]);
                wmma::mma_sync(acc[1][nn], a1, bfr, acc[1][nn]);
            }
        }
        __syncthreads();
    }
#pragma unroll
    for (int m = 0; m < 2; m++)
#pragma unroll
        for (int nn = 0; nn < 2; nn++)
            wmma::store_matrix_sync(sC + (wr * 32 + m * 16) * 68 + wc * 32 + nn * 16,
                                    acc[m][nn], 68, wmma::mem_row_major);
    __syncthreads();
    const float* xb   = x   + (size_t)b * C_ * N_;
    float*       outb = out + (size_t)b * C_ * N_;
    for (int idx = tid; idx < 128 * 64; idx += 256) {
        int il = idx & 127, ol = idx >> 7;
        float v = sC[il * 68 + ol] + bp[o0 + ol] + xb[(size_t)(o0 + ol) * N_ + i0 + il];
        outb[(size_t)(o0 + ol) * N_ + i0 + il] = v;
    }
}

// ---------------------------------------------------------------------------
// K4: flash attention (no-max softmax).  grid (64, 4), 256 threads, 1 CTA/SM
//   per block: 64 queries; stream 64-key tiles; O accum (fp32) split by c across 8 warps
// ---------------------------------------------------------------------------
#define FLASH_SMEM_BYTES 177408

__global__ __launch_bounds__(256, 1) void flash_kernel() {
    extern __shared__ char smraw[];
    bf16*  sQ = (bf16*)smraw;          // [64][520]
    bf16*  sV = sQ + 64 * 520;         // [64][520]
    bf16*  sK = sV + 64 * 520;         // [64][136]  (128-col chunk of K)
    bf16*  sP = sK + 64 * 136;         // [64][72]
    float* sS = (float*)(sP + 64 * 72);// [64][68]
    float* sl = sS + 64 * 68;          // [64]

    int b  = blockIdx.y;
    int i0 = blockIdx.x * 64;
    const bf16* qb = g_q + ((size_t)b * N_ + i0) * C_;
    const bf16* kb = g_k + (size_t)b * N_ * C_;
    const bf16* vb = g_v + (size_t)b * N_ * C_;

    int tid = threadIdx.x, warp = tid >> 5;
    const int sm0 = (warp >> 1) * 16;   // S row block
    const int sn0 = (warp & 1) * 32;    // S col half

    // load Q tile
#pragma unroll
    for (int t = 0; t < 16; t++) {
        int idx = tid + 256 * t;
        int r = idx >> 6, c8 = idx & 63;
        *(uint4*)(sQ + r * 520 + c8 * 8) = *(const uint4*)(qb + (size_t)r * C_ + c8 * 8);
    }
    if (tid < 64) sl[tid] = 0.f;

    wmma::fragment<wmma::accumulator, 16, 16, 16, float> oacc[4][4];
#pragma unroll
    for (int m = 0; m < 4; m++)
#pragma unroll
        for (int n = 0; n < 4; n++) wmma::fill_fragment(oacc[m][n], 0.f);
    __syncthreads();

    for (int jt = 0; jt < 64; jt++) {
        const bf16* kjb = kb + (size_t)jt * 64 * C_;
        const bf16* vjb = vb + (size_t)jt * 64 * C_;

        // ---- S = Q K^T (accumulate over 4 c-chunks of 128) ----
        wmma::fragment<wmma::accumulator, 16, 16, 16, float> sacc[2];
        wmma::fill_fragment(sacc[0], 0.f);
        wmma::fill_fragment(sacc[1], 0.f);
#pragma unroll
        for (int cc = 0; cc < 4; cc++) {
#pragma unroll
            for (int t = 0; t < 4; t++) {
                int idx = tid + 256 * t;
                int r = idx >> 4, c8 = idx & 15;
                *(uint4*)(sK + r * 136 + c8 * 8) =
                    *(const uint4*)(kjb + (size_t)r * C_ + cc * 128 + c8 * 8);
            }
            __syncthreads();
#pragma unroll
            for (int ks = 0; ks < 8; ks++) {
                wmma::fragment<wmma::matrix_a, 16, 16, 16, bf16, wmma::row_major> af;
                wmma::load_matrix_sync(af, sQ + sm0 * 520 + cc * 128 + ks * 16, 520);
#pragma unroll
                for (int nn = 0; nn < 2; nn++) {
                    wmma::fragment<wmma::matrix_b, 16, 16, 16, bf16, wmma::col_major> bfr;
                    wmma::load_matrix_sync(bfr, sK + (sn0 + nn * 16) * 136 + ks * 16, 136);
                    wmma::mma_sync(sacc[nn], af, bfr, sacc[nn]);
                }
            }
            __syncthreads();
        }

        // store S, load V tile
        wmma::store_matrix_sync(sS + sm0 * 68 + sn0,      sacc[0], 68, wmma::mem_row_major);
        wmma::store_matrix_sync(sS + sm0 * 68 + sn0 + 16, sacc[1], 68, wmma::mem_row_major);
#pragma unroll
        for (int t = 0; t < 16; t++) {
            int idx = tid + 256 * t;
            int r = idx >> 6, c8 = idx & 63;
            *(uint4*)(sV + r * 520 + c8 * 8) = *(const uint4*)(vjb + (size_t)r * C_ + c8 * 8);
        }
        __syncthreads();

        // ---- softmax numerators: P = exp(S * rscale); accumulate l ----
        {
            int row = tid >> 2, qq = tid & 3;
            float sum = 0.f;
#pragma unroll
            for (int u = 0; u < 16; u++) {
                int col = qq * 16 + u;
                float p = __expf(sS[row * 68 + col] * RSCALE);
                sum += p;
                sP[row * 72 + col] = __float2bfloat16(p);
            }
            sum += __shfl_xor_sync(0xffffffffu, sum, 1);
            sum += __shfl_xor_sync(0xffffffffu, sum, 2);
            if (qq == 0) sl[row] += sum;
        }
        __syncthreads();

        // ---- O += P @ V  (each warp owns c-slice [64*warp, 64*warp+64)) ----
#pragma unroll
        for (int ks = 0; ks < 4; ks++) {
            wmma::fragment<wmma::matrix_a, 16, 16, 16, bf16, wmma::row_major> pa[4];
#pragma unroll
            for (int m = 0; m < 4; m++)
                wmma::load_matrix_sync(pa[m], sP + (m * 16) * 72 + ks * 16, 72);
#pragma unroll
            for (int nn = 0; nn < 4; nn++) {
                wmma::fragment<wmma::matrix_b, 16, 16, 16, bf16, wmma::row_major> vf;
                wmma::load_matrix_sync(vf, sV + (ks * 16) * 520 + warp * 64 + nn * 16, 520);
#pragma unroll
                for (int m = 0; m < 4; m++)
                    wmma::mma_sync(oacc[m][nn], pa[m], vf, oacc[m][nn]);
            }
        }
        __syncthreads();
    }

    // epilogue: dump unnormalized O + denominators
    float* ob = g_o + ((size_t)b * N_ + i0) * C_;
#pragma unroll
    for (int m = 0; m < 4; m++)
#pragma unroll
        for (int nn = 0; nn < 4; nn++)
            wmma::store_matrix_sync(ob + (size_t)(m * 16) * C_ + warp * 64 + nn * 16,
                                    oacc[m][nn], C_, wmma::mem_row_major);
    if (tid < 64) g_l[(size_t)b * N_ + i0 + tid] = sl[tid];
}

// ---------------------------------------------------------------------------
// K5: normalize attn rows, convert to bf16, write into g_hn (reuse). grid (8192, 256)
// ---------------------------------------------------------------------------
__global__ void norm_attn() {
    size_t idx = (size_t)blockIdx.x * 256 + threadIdx.x;   // over B*N*C/4
    float4 o = ((const float4*)g_o)[idx];
    size_t rowI = idx / (C_ / 4);                          // = (idx*4)/C_
    float inv = 1.f / g_l[rowI];
    bf16 tmp[4];
    tmp[0] = __float2bfloat16(o.x * inv);
    tmp[1] = __float2bfloat16(o.y * inv);
    tmp[2] = __float2bfloat16(o.z * inv);
    tmp[3] = __float2bfloat16(o.w * inv);
    ((uint2*)g_hn)[idx] = *(uint2*)tmp;
}

// ---------------------------------------------------------------------------
// Launch
// ---------------------------------------------------------------------------
extern "C" void kernel_launch(void* const* d_in, const int* in_sizes, int n_in,
                              void* d_out, int out_size) {
    const float* x  = (const float*)d_in[0];
    const float* gs = (const float*)d_in[1];
    const float* gb = (const float*)d_in[2];
    const float* wq = (const float*)d_in[3];
    const float* bq = (const float*)d_in[4];
    const float* wk = (const float*)d_in[5];
    const float* bk = (const float*)d_in[6];
    const float* wv = (const float*)d_in[7];
    const float* bv = (const float*)d_in[8];
    const float* wp = (const float*)d_in[9];
    const float* bp = (const float*)d_in[10];
    float* out = (float*)d_out;

    cudaFuncSetAttribute(flash_kernel, cudaFuncAttributeMaxDynamicSharedMemorySize,
                         FLASH_SMEM_BYTES);

    prep_weights<<<dim3(16, 16, 4), dim3(32, 8)>>>(wq, wk, wv, wp);
    gn_stats<<<B_ * G_, 256>>>(x);
    gn_apply<<<dim3(N_ / 32, C_ / 32, B_), dim3(32, 8)>>>(x, gs, gb);
    gemm_qkv<<<dim3(N_ / 128, C_ / 64, B_ * 3), 256, GEMM_SMEM_BYTES>>>(bq, bk, bv);
    flash_kernel<<<dim3(N_ / 64, B_), 256, FLASH_SMEM_BYTES>>>();
    norm_attn<<<(B_ * (size_t)N_ * C_ / 4) / 256, 256>>>();
    gemm_proj<<<dim3(N_ / 128, C_ / 64, B_), 256, GEMM_SMEM_BYTES>>>(x, bp, out);
}

// round 7
// speedup vs baseline: 1.6183x; 1.6183x over previous
#include <cuda_runtime.h>
#include <cuda_bf16.h>
#include <mma.h>
#include <cstdint>

using namespace nvcuda;
using bf16 = __nv_bfloat16;

#define B_  4
#define C_  512
#define N_  4096
#define G_  32
#define CPG 16           // channels per group = C_/G_

static __device__ __align__(16) bf16  g_hn[(size_t)B_*N_*C_];   // normed x, token-major [b][i][c]; reused for attn output
static __device__ __align__(16) bf16  g_q [(size_t)B_*N_*C_];   // [b][i][c]
static __device__ __align__(16) bf16  g_k [(size_t)B_*N_*C_];
static __device__ __align__(16) bf16  g_v [(size_t)B_*N_*C_];
static __device__ __align__(16) bf16  g_wt[4][C_*C_];           // transposed bf16 weights: Wt[c][o] = W[o][c]
static __device__ float g_mean[B_*G_];
static __device__ float g_rstd[B_*G_];

#define RSCALE 0.044194173824159216f   // 1/sqrt(512)

// ---------------------------------------------------------------------------
// K0: weight transpose + bf16 convert.  grid (16,16,4), block (32,8)
// ---------------------------------------------------------------------------
__global__ void prep_weights(const float* __restrict__ wq, const float* __restrict__ wk,
                             const float* __restrict__ wv, const float* __restrict__ wp) {
    __shared__ float t[32][33];
    const float* Wsel[4] = {wq, wk, wv, wp};
    const float* src = Wsel[blockIdx.z];
    int o0 = blockIdx.x * 32, c0 = blockIdx.y * 32;
    int tx = threadIdx.x, ty = threadIdx.y;
#pragma unroll
    for (int k = 0; k < 4; k++)
        t[ty + 8*k][tx] = src[(size_t)(o0 + ty + 8*k) * C_ + c0 + tx];   // t[o_local][c_local]
    __syncthreads();
#pragma unroll
    for (int k = 0; k < 4; k++)
        g_wt[blockIdx.z][(size_t)(c0 + ty + 8*k) * C_ + o0 + tx] = __float2bfloat16(t[tx][ty + 8*k]);
}

// ---------------------------------------------------------------------------
// K1: groupnorm statistics. grid (B*G = 128), block 256
// ---------------------------------------------------------------------------
__global__ void gn_stats(const float* __restrict__ x) {
    int bg = blockIdx.x;
    int b = bg / G_, g = bg % G_;
    const float* base = x + (size_t)b * C_ * N_ + (size_t)g * CPG * N_;
    float s = 0.f, ss = 0.f;
    for (int i = threadIdx.x; i < CPG * N_; i += blockDim.x) {
        float v = base[i];
        s += v; ss += v * v;
    }
#pragma unroll
    for (int o = 16; o; o >>= 1) {
        s  += __shfl_xor_sync(0xffffffffu, s,  o);
        ss += __shfl_xor_sync(0xffffffffu, ss, o);
    }
    __shared__ float rs[8], rss[8];
    int w = threadIdx.x >> 5, lane = threadIdx.x & 31;
    if (lane == 0) { rs[w] = s; rss[w] = ss; }
    __syncthreads();
    if (w == 0) {
        s  = (lane < 8) ? rs[lane]  : 0.f;
        ss = (lane < 8) ? rss[lane] : 0.f;
#pragma unroll
        for (int o = 4; o; o >>= 1) {
            s  += __shfl_xor_sync(0xffffffffu, s,  o);
            ss += __shfl_xor_sync(0xffffffffu, ss, o);
        }
        if (lane == 0) {
            const float M = (float)(CPG * N_);
            float m = s / M;
            float var = ss / M - m * m;
            g_mean[bg] = m;
            g_rstd[bg] = rsqrtf(var + 1e-6f);
        }
    }
}

// ---------------------------------------------------------------------------
// K2: apply groupnorm + transpose to token-major bf16.  grid (128,16,4), block (32,8)
// ---------------------------------------------------------------------------
__global__ void gn_apply(const float* __restrict__ x, const float* __restrict__ gs,
                         const float* __restrict__ gb) {
    __shared__ float t[32][33];
    int b = blockIdx.z;
    int i0 = blockIdx.x * 32, c0 = blockIdx.y * 32;
    int tx = threadIdx.x, ty = threadIdx.y;
    const float* xb = x + (size_t)b * C_ * N_;
#pragma unroll
    for (int k = 0; k < 4; k++)
        t[ty + 8*k][tx] = xb[(size_t)(c0 + ty + 8*k) * N_ + i0 + tx];   // t[c_local][i_local]
    __syncthreads();
#pragma unroll
    for (int k = 0; k < 4; k++) {
        int c = c0 + tx;
        int i = i0 + ty + 8*k;
        int bg = b * G_ + c / CPG;
        float m = g_mean[bg], r = g_rstd[bg];
        float val = (t[tx][ty + 8*k] - m) * r * gs[c] + gb[c];
        g_hn[((size_t)b * N_ + i) * C_ + c] = __float2bfloat16(val);
    }
}

// ---------------------------------------------------------------------------
// Shared GEMM tiling: BM=128, BN=64, BK=32, 8 warps, warp tile 32x32
//   C[i][o] = sum_c A[i][c] * Wt[c][o]
// ---------------------------------------------------------------------------
#define GEMM_SMEM_BYTES (128 * 68 * 4)   // staging dominates (34816 B)

// K3: QKV projection -> bf16 [b][i][o].  grid (32, 8, 12), block 256
__global__ __launch_bounds__(256) void gemm_qkv(const float* __restrict__ bq,
                                                const float* __restrict__ bk,
                                                const float* __restrict__ bv) {
    extern __shared__ char smraw[];
    bf16*  sA = (bf16*)smraw;                     // [128][48]
    bf16*  sB = (bf16*)(smraw + 128 * 48 * 2);    // [32][72]
    float* sC = (float*)smraw;                    // [128][68] (reuses sA/sB)

    int bz = blockIdx.z;
    int b = bz / 3, which = bz % 3;
    const bf16* A  = g_hn + (size_t)b * N_ * C_;
    const bf16* Wt = g_wt[which];
    bf16* outp = (which == 0 ? g_q : which == 1 ? g_k : g_v) + (size_t)b * N_ * C_;
    const float* bias = (which == 0 ? bq : which == 1 ? bk : bv);

    int i0 = blockIdx.x * 128, o0 = blockIdx.y * 64;
    int tid = threadIdx.x, warp = tid >> 5;
    int wr = warp >> 1, wc = warp & 1;

    wmma::fragment<wmma::accumulator, 16, 16, 16, float> acc[2][2];
#pragma unroll
    for (int m = 0; m < 2; m++)
#pragma unroll
        for (int n = 0; n < 2; n++) wmma::fill_fragment(acc[m][n], 0.f);

    for (int k0 = 0; k0 < 16; k0++) {
        int kk = k0 * 32;
#pragma unroll
        for (int t = 0; t < 2; t++) {
            int idx = tid + 256 * t;
            int r = idx >> 2, c8 = idx & 3;
            *(uint4*)(sA + r * 48 + c8 * 8) =
                *(const uint4*)(A + (size_t)(i0 + r) * C_ + kk + c8 * 8);
        }
        {
            int r = tid >> 3, c8 = tid & 7;
            *(uint4*)(sB + r * 72 + c8 * 8) =
                *(const uint4*)(Wt + (size_t)(kk + r) * C_ + o0 + c8 * 8);
        }
        __syncthreads();
#pragma unroll
        for (int ks = 0; ks < 2; ks++) {
            wmma::fragment<wmma::matrix_a, 16, 16, 16, bf16, wmma::row_major> a0, a1;
            wmma::load_matrix_sync(a0, sA + (wr * 32     ) * 48 + ks * 16, 48);
            wmma::load_matrix_sync(a1, sA + (wr * 32 + 16) * 48 + ks * 16, 48);
#pragma unroll
            for (int nn = 0; nn < 2; nn++) {
                wmma::fragment<wmma::matrix_b, 16, 16, 16, bf16, wmma::row_major> bfr;
                wmma::load_matrix_sync(bfr, sB + (ks * 16) * 72 + wc * 32 + nn * 16, 72);
                wmma::mma_sync(acc[0][nn], a0, bfr, acc[0][nn]);
                wmma::mma_sync(acc[1][nn], a1, bfr, acc[1][nn]);
            }
        }
        __syncthreads();
    }
#pragma unroll
    for (int m = 0; m < 2; m++)
#pragma unroll
        for (int nn = 0; nn < 2; nn++)
            wmma::store_matrix_sync(sC + (wr * 32 + m * 16) * 68 + wc * 32 + nn * 16,
                                    acc[m][nn], 68, wmma::mem_row_major);
    __syncthreads();
    for (int idx = tid; idx < 128 * 64; idx += 256) {
        int r = idx >> 6, cl = idx & 63;
        outp[(size_t)(i0 + r) * C_ + o0 + cl] =
            __float2bfloat16(sC[r * 68 + cl] + bias[o0 + cl]);
    }
}

// K6: proj GEMM + bias + residual, transposed store into d_out. grid (32, 8, 4)
__global__ __launch_bounds__(256) void gemm_proj(const float* __restrict__ x,
                                                 const float* __restrict__ bp,
                                                 float* __restrict__ out) {
    extern __shared__ char smraw[];
    bf16*  sA = (bf16*)smraw;
    bf16*  sB = (bf16*)(smraw + 128 * 48 * 2);
    float* sC = (float*)smraw;

    int b = blockIdx.z;
    const bf16* A  = g_hn + (size_t)b * N_ * C_;   // g_hn reused: holds normalized attn out (bf16)
    const bf16* Wt = g_wt[3];

    int i0 = blockIdx.x * 128, o0 = blockIdx.y * 64;
    int tid = threadIdx.x, warp = tid >> 5;
    int wr = warp >> 1, wc = warp & 1;

    wmma::fragment<wmma::accumulator, 16, 16, 16, float> acc[2][2];
#pragma unroll
    for (int m = 0; m < 2; m++)
#pragma unroll
        for (int n = 0; n < 2; n++) wmma::fill_fragment(acc[m][n], 0.f);

    for (int k0 = 0; k0 < 16; k0++) {
        int kk = k0 * 32;
#pragma unroll
        for (int t = 0; t < 2; t++) {
            int idx = tid + 256 * t;
            int r = idx >> 2, c8 = idx & 3;
            *(uint4*)(sA + r * 48 + c8 * 8) =
                *(const uint4*)(A + (size_t)(i0 + r) * C_ + kk + c8 * 8);
        }
        {
            int r = tid >> 3, c8 = tid & 7;
            *(uint4*)(sB + r * 72 + c8 * 8) =
                *(const uint4*)(Wt + (size_t)(kk + r) * C_ + o0 + c8 * 8);
        }
        __syncthreads();
#pragma unroll
        for (int ks = 0; ks < 2; ks++) {
            wmma::fragment<wmma::matrix_a, 16, 16, 16, bf16, wmma::row_major> a0, a1;
            wmma::load_matrix_sync(a0, sA + (wr * 32     ) * 48 + ks * 16, 48);
            wmma::load_matrix_sync(a1, sA + (wr * 32 + 16) * 48 + ks * 16, 48);
#pragma unroll
            for (int nn = 0; nn < 2; nn++) {
                wmma::fragment<wmma::matrix_b, 16, 16, 16, bf16, wmma::row_major> bfr;
                wmma::load_matrix_sync(bfr, sB + (ks * 16) * 72 + wc * 32 + nn * 16, 72);
                wmma::mma_sync(acc[0][nn], a0, bfr, acc[0][nn]);
                wmma::mma_sync(acc[1][nn], a1, bfr, acc[1][nn]);
            }
        }
        __syncthreads();
    }
#pragma unroll
    for (int m = 0; m < 2; m++)
#pragma unroll
        for (int nn = 0; nn < 2; nn++)
            wmma::store_matrix_sync(sC + (wr * 32 + m * 16) * 68 + wc * 32 + nn * 16,
                                    acc[m][nn], 68, wmma::mem_row_major);
    __syncthreads();
    const float* xb   = x   + (size_t)b * C_ * N_;
    float*       outb = out + (size_t)b * C_ * N_;
    for (int idx = tid; idx < 128 * 64; idx += 256) {
        int il = idx & 127, ol = idx >> 7;
        float v = sC[il * 68 + ol] + bp[o0 + ol] + xb[(size_t)(o0 + ol) * N_ + i0 + il];
        outb[(size_t)(o0 + ol) * N_ + i0 + il] = v;
    }
}

// ---------------------------------------------------------------------------
// K4: flash attention, raw mma.m16n8k16, register softmax (no-max, exp direct).
//   grid (64, 4), 256 threads, 1 CTA/SM.
//   Per CTA: 64 queries resident; stream 64-key tiles with cp.async overlap.
//   S phase: warps split rows(4) x keys(2), 16x32 each, accum in regs.
//   PV phase: warps split C into 8 slices of 64; P shared via smem bf16.
// ---------------------------------------------------------------------------
#define QS 520   // bf16 row stride for Q/K/V tiles (512 + 8 pad)
#define PS 72    // bf16 row stride for P tile
// layout: sQ[64*QS] sK[64*QS] sV[64*QS] sP[64*PS] sl[64] sPart[128]
#define OFF_K   (64 * QS * 2)
#define OFF_V   (2 * 64 * QS * 2)
#define OFF_P   (3 * 64 * QS * 2)
#define OFF_L   (OFF_P + 64 * PS * 2)
#define OFF_LP  (OFF_L + 64 * 4)
#define FLASH_SMEM_BYTES (OFF_LP + 128 * 4)   // 209664

__device__ __forceinline__ uint32_t smem_u32(const void* p) {
    return (uint32_t)__cvta_generic_to_shared(p);
}
__device__ __forceinline__ void cpa16(uint32_t dst, const void* src) {
    asm volatile("cp.async.cg.shared.global [%0], [%1], 16;\n" :: "r"(dst), "l"(src));
}
#define CP_COMMIT() asm volatile("cp.async.commit_group;\n")
#define CP_WAIT0()  asm volatile("cp.async.wait_group 0;\n")

__device__ __forceinline__ void ldsm4(uint32_t a, uint32_t* r) {
    asm volatile("ldmatrix.sync.aligned.m8n8.x4.shared.b16 {%0,%1,%2,%3}, [%4];\n"
        : "=r"(r[0]), "=r"(r[1]), "=r"(r[2]), "=r"(r[3]) : "r"(a));
}
__device__ __forceinline__ void ldsm4t(uint32_t a, uint32_t* r) {
    asm volatile("ldmatrix.sync.aligned.m8n8.x4.trans.shared.b16 {%0,%1,%2,%3}, [%4];\n"
        : "=r"(r[0]), "=r"(r[1]), "=r"(r[2]), "=r"(r[3]) : "r"(a));
}
__device__ __forceinline__ void mma16816(float* d, const uint32_t* a, uint32_t b0, uint32_t b1) {
    asm volatile("mma.sync.aligned.m16n8k16.row.col.f32.bf16.bf16.f32 "
        "{%0,%1,%2,%3}, {%4,%5,%6,%7}, {%8,%9}, {%0,%1,%2,%3};\n"
        : "+f"(d[0]), "+f"(d[1]), "+f"(d[2]), "+f"(d[3])
        : "r"(a[0]), "r"(a[1]), "r"(a[2]), "r"(a[3]), "r"(b0), "r"(b1));
}

__global__ __launch_bounds__(256, 1) void flash_kernel() {
    extern __shared__ char sm[];
    uint32_t*  sPw   = (uint32_t*)(sm + OFF_P);
    float*     sl    = (float*)(sm + OFF_L);
    float*     sPart = (float*)(sm + OFF_LP);

    const int b  = blockIdx.y;
    const int i0 = blockIdx.x * 64;
    const bf16* qg = g_q + ((size_t)b * N_ + i0) * C_;
    const bf16* kg = g_k + (size_t)b * N_ * C_;
    const bf16* vg = g_v + (size_t)b * N_ * C_;

    const int tid = threadIdx.x, lane = tid & 31, warp = tid >> 5;
    const int g = lane >> 2, q4 = lane & 3;

    const uint32_t sQa = smem_u32(sm);
    const uint32_t sKa = sQa + OFF_K;
    const uint32_t sVa = sQa + OFF_V;
    const uint32_t sPa = sQa + OFF_P;

    // cp.async: Q tile, then K(0)
    const int ldr = tid >> 2;              // unused helper kept minimal
    (void)ldr;
#pragma unroll
    for (int t = 0; t < 16; t++) {
        int idx = tid + 256 * t;
        int r = idx >> 6, c8 = idx & 63;
        cpa16(sQa + (r * QS + c8 * 8) * 2, qg + (size_t)r * C_ + c8 * 8);
    }
    CP_COMMIT();
#pragma unroll
    for (int t = 0; t < 16; t++) {
        int idx = tid + 256 * t;
        int r = idx >> 6, c8 = idx & 63;
        cpa16(sKa + (r * QS + c8 * 8) * 2, kg + (size_t)r * C_ + c8 * 8);
    }
    CP_COMMIT();
    if (tid < 64) sl[tid] = 0.f;

    // O accumulators: [m-block 4][n-block 8][4]
    float oacc[4][8][4];
#pragma unroll
    for (int mb = 0; mb < 4; mb++)
#pragma unroll
        for (int nb = 0; nb < 8; nb++)
#pragma unroll
            for (int e = 0; e < 4; e++) oacc[mb][nb][e] = 0.f;

    // S-phase geometry
    const int sm0 = (warp >> 1) * 16;
    const int sn0 = (warp & 1) * 32;
    const int wc  = warp & 1;
    // PV-phase geometry
    const int cw = warp * 64;

    // lane-resident ldmatrix base addresses
    const uint32_t aQ = sQa + ((sm0 + (lane & 15)) * QS + (lane >> 4) * 8) * 2;
    const uint32_t aK = sKa + ((sn0 + (lane & 7) + ((lane >> 4) << 3)) * QS
                               + ((lane >> 3) & 1) * 8) * 2;
    const uint32_t aP = sPa + (((lane & 15)) * PS + (lane >> 4) * 8) * 2;
    const uint32_t aV = sVa + (((lane & 7) + ((lane >> 3) & 1) * 8) * QS
                               + cw + (lane >> 4) * 8) * 2;

    const int pw1 = (sm0 + g) * (PS / 2) + (sn0 >> 1) + q4;   // uint32 word index, row g
    const int pw2 = pw1 + 8 * (PS / 2);                        // row g+8

    CP_WAIT0();
    __syncthreads();

    for (int jt = 0; jt < 64; jt++) {
        // prefetch V(jt) — not needed until after S
#pragma unroll
        for (int t = 0; t < 16; t++) {
            int idx = tid + 256 * t;
            int r = idx >> 6, c8 = idx & 63;
            cpa16(sVa + (r * QS + c8 * 8) * 2,
                  vg + ((size_t)(jt * 64 + r)) * C_ + c8 * 8);
        }
        CP_COMMIT();

        // ---- S = Q K^T : per warp 16x32, accum in regs, double-buffered frags ----
        float sacc[4][4];
#pragma unroll
        for (int nb = 0; nb < 4; nb++)
#pragma unroll
            for (int e = 0; e < 4; e++) sacc[nb][e] = 0.f;

        uint32_t afr[2][4], bfr[2][8];
        ldsm4(aQ, afr[0]);
        ldsm4(aK, bfr[0]);
        ldsm4(aK + 16 * QS * 2, bfr[0] + 4);
#pragma unroll
        for (int ks = 0; ks < 32; ks++) {
            int cur = ks & 1, nxt = cur ^ 1;
            if (ks < 31) {
                uint32_t o = (uint32_t)(ks + 1) * 32;
                ldsm4(aQ + o, afr[nxt]);
                ldsm4(aK + o, bfr[nxt]);
                ldsm4(aK + o + 16 * QS * 2, bfr[nxt] + 4);
            }
            mma16816(sacc[0], afr[cur], bfr[cur][0], bfr[cur][1]);
            mma16816(sacc[1], afr[cur], bfr[cur][2], bfr[cur][3]);
            mma16816(sacc[2], afr[cur], bfr[cur][4], bfr[cur][5]);
            mma16816(sacc[3], afr[cur], bfr[cur][6], bfr[cur][7]);
        }

        CP_WAIT0();   // V(jt) landed (this thread's copies)

        // ---- register softmax: p = exp(s/sqrt(C)); write bf16 P; row partials ----
        float l1 = 0.f, l2 = 0.f;
#pragma unroll
        for (int nb = 0; nb < 4; nb++) {
            float e0 = __expf(sacc[nb][0] * RSCALE);
            float e1 = __expf(sacc[nb][1] * RSCALE);
            float e2 = __expf(sacc[nb][2] * RSCALE);
            float e3 = __expf(sacc[nb][3] * RSCALE);
            l1 += e0 + e1; l2 += e2 + e3;
            __nv_bfloat162 p01 = __floats2bfloat162_rn(e0, e1);
            __nv_bfloat162 p23 = __floats2bfloat162_rn(e2, e3);
            sPw[pw1 + nb * 4] = *(uint32_t*)&p01;
            sPw[pw2 + nb * 4] = *(uint32_t*)&p23;
        }
        l1 += __shfl_xor_sync(0xffffffffu, l1, 1);
        l1 += __shfl_xor_sync(0xffffffffu, l1, 2);
        l2 += __shfl_xor_sync(0xffffffffu, l2, 1);
        l2 += __shfl_xor_sync(0xffffffffu, l2, 2);
        if (q4 == 0) {
            sPart[wc * 64 + sm0 + g]     = l1;
            sPart[wc * 64 + sm0 + g + 8] = l2;
        }
        __syncthreads();                    // P + sPart visible, V visible
        if (tid < 64) sl[tid] += sPart[tid] + sPart[64 + tid];

        // prefetch K(jt+1) — sK free (S done in all warps)
        if (jt < 63) {
#pragma unroll
            for (int t = 0; t < 16; t++) {
                int idx = tid + 256 * t;
                int r = idx >> 6, c8 = idx & 63;
                cpa16(sKa + (r * QS + c8 * 8) * 2,
                      kg + ((size_t)((jt + 1) * 64 + r)) * C_ + c8 * 8);
            }
        }
        CP_COMMIT();

        // ---- O += P @ V : per warp, 64 rows x 64-col C slice ----
#pragma unroll
        for (int ks = 0; ks < 4; ks++) {
            uint32_t pa[4][4];
#pragma unroll
            for (int mb = 0; mb < 4; mb++)
                ldsm4(aP + (uint32_t)(mb * 16 * PS * 2 + ks * 32), pa[mb]);
#pragma unroll
            for (int nb2 = 0; nb2 < 4; nb2++) {
                uint32_t vb[4];
                ldsm4t(aV + (uint32_t)(ks * 16 * QS * 2 + nb2 * 32), vb);
#pragma unroll
                for (int mb = 0; mb < 4; mb++) {
                    mma16816(oacc[mb][nb2 * 2],     pa[mb], vb[0], vb[1]);
                    mma16816(oacc[mb][nb2 * 2 + 1], pa[mb], vb[2], vb[3]);
                }
            }
        }

        CP_WAIT0();       // K(jt+1) landed (this thread)
        __syncthreads();  // all copies visible; sV/sP safe to overwrite
    }

    // ---- epilogue: normalize by 1/l, write bf16 straight into g_hn ----
    float inv1[4], inv2[4];
#pragma unroll
    for (int mb = 0; mb < 4; mb++) {
        inv1[mb] = 1.f / sl[mb * 16 + g];
        inv2[mb] = 1.f / sl[mb * 16 + g + 8];
    }
    bf16* og = g_hn + ((size_t)b * N_ + i0) * C_;
#pragma unroll
    for (int mb = 0; mb < 4; mb++) {
        int r1 = mb * 16 + g;
#pragma unroll
        for (int nb = 0; nb < 8; nb++) {
            int c = cw + nb * 8 + 2 * q4;
            __nv_bfloat162 v1 = __floats2bfloat162_rn(oacc[mb][nb][0] * inv1[mb],
                                                      oacc[mb][nb][1] * inv1[mb]);
            __nv_bfloat162 v2 = __floats2bfloat162_rn(oacc[mb][nb][2] * inv2[mb],
                                                      oacc[mb][nb][3] * inv2[mb]);
            *(uint32_t*)(og + (size_t)r1 * C_ + c)       = *(uint32_t*)&v1;
            *(uint32_t*)(og + (size_t)(r1 + 8) * C_ + c) = *(uint32_t*)&v2;
        }
    }
}

// ---------------------------------------------------------------------------
// Launch
// ---------------------------------------------------------------------------
extern "C" void kernel_launch(void* const* d_in, const int* in_sizes, int n_in,
                              void* d_out, int out_size) {
    const float* x  = (const float*)d_in[0];
    const float* gs = (const float*)d_in[1];
    const float* gb = (const float*)d_in[2];
    const float* wq = (const float*)d_in[3];
    const float* bq = (const float*)d_in[4];
    const float* wk = (const float*)d_in[5];
    const float* bk = (const float*)d_in[6];
    const float* wv = (const float*)d_in[7];
    const float* bv = (const float*)d_in[8];
    const float* wp = (const float*)d_in[9];
    const float* bp = (const float*)d_in[10];
    float* out = (float*)d_out;

    cudaFuncSetAttribute(flash_kernel, cudaFuncAttributeMaxDynamicSharedMemorySize,
                         FLASH_SMEM_BYTES);

    prep_weights<<<dim3(16, 16, 4), dim3(32, 8)>>>(wq, wk, wv, wp);
    gn_stats<<<B_ * G_, 256>>>(x);
    gn_apply<<<dim3(N_ / 32, C_ / 32, B_), dim3(32, 8)>>>(x, gs, gb);
    gemm_qkv<<<dim3(N_ / 128, C_ / 64, B_ * 3), 256, GEMM_SMEM_BYTES>>>(bq, bk, bv);
    flash_kernel<<<dim3(N_ / 64, B_), 256, FLASH_SMEM_BYTES>>>();
    gemm_proj<<<dim3(N_ / 128, C_ / 64, B_), 256, GEMM_SMEM_BYTES>>>(x, bp, out);
}

// round 8
// speedup vs baseline: 1.8882x; 1.1668x over previous
#include <cuda_runtime.h>
#include <cuda_bf16.h>
#include <cstdint>

using bf16 = __nv_bfloat16;

#define B_  4
#define C_  512
#define N_  4096
#define G_  32
#define CPG 16           // channels per group = C_/G_

static __device__ __align__(16) bf16  g_hn[(size_t)B_*N_*C_];   // normed x, token-major [b][i][c]; reused for attn output
static __device__ __align__(16) bf16  g_q [(size_t)B_*N_*C_];   // [b][i][c]
static __device__ __align__(16) bf16  g_k [(size_t)B_*N_*C_];
static __device__ __align__(16) bf16  g_v [(size_t)B_*N_*C_];
static __device__ __align__(16) bf16  g_wt[4][C_*C_];           // transposed bf16 weights: Wt[c][o] = W[o][c]
static __device__ float g_mean[B_*G_];
static __device__ float g_rstd[B_*G_];

#define RSCALE 0.044194173824159216f   // 1/sqrt(512)

// ---------------------------------------------------------------------------
// common PTX helpers
// ---------------------------------------------------------------------------
__device__ __forceinline__ uint32_t smem_u32(const void* p) {
    return (uint32_t)__cvta_generic_to_shared(p);
}
__device__ __forceinline__ void cpa16(uint32_t dst, const void* src) {
    asm volatile("cp.async.cg.shared.global [%0], [%1], 16;\n" :: "r"(dst), "l"(src));
}
#define CP_COMMIT() asm volatile("cp.async.commit_group;\n")
#define CP_WAIT0()  asm volatile("cp.async.wait_group 0;\n")
#define CP_WAIT1()  asm volatile("cp.async.wait_group 1;\n")

__device__ __forceinline__ void ldsm4(uint32_t a, uint32_t* r) {
    asm volatile("ldmatrix.sync.aligned.m8n8.x4.shared.b16 {%0,%1,%2,%3}, [%4];\n"
        : "=r"(r[0]), "=r"(r[1]), "=r"(r[2]), "=r"(r[3]) : "r"(a));
}
__device__ __forceinline__ void ldsm4t(uint32_t a, uint32_t* r) {
    asm volatile("ldmatrix.sync.aligned.m8n8.x4.trans.shared.b16 {%0,%1,%2,%3}, [%4];\n"
        : "=r"(r[0]), "=r"(r[1]), "=r"(r[2]), "=r"(r[3]) : "r"(a));
}
__device__ __forceinline__ void mma16816(float* d, const uint32_t* a, uint32_t b0, uint32_t b1) {
    asm volatile("mma.sync.aligned.m16n8k16.row.col.f32.bf16.bf16.f32 "
        "{%0,%1,%2,%3}, {%4,%5,%6,%7}, {%8,%9}, {%0,%1,%2,%3};\n"
        : "+f"(d[0]), "+f"(d[1]), "+f"(d[2]), "+f"(d[3])
        : "r"(a[0]), "r"(a[1]), "r"(a[2]), "r"(a[3]), "r"(b0), "r"(b1));
}

// ---------------------------------------------------------------------------
// K0: weight transpose + bf16 convert.  grid (16,16,4), block (32,8)
// ---------------------------------------------------------------------------
__global__ void prep_weights(const float* __restrict__ wq, const float* __restrict__ wk,
                             const float* __restrict__ wv, const float* __restrict__ wp) {
    __shared__ float t[32][33];
    const float* Wsel[4] = {wq, wk, wv, wp};
    const float* src = Wsel[blockIdx.z];
    int o0 = blockIdx.x * 32, c0 = blockIdx.y * 32;
    int tx = threadIdx.x, ty = threadIdx.y;
#pragma unroll
    for (int k = 0; k < 4; k++)
        t[ty + 8*k][tx] = src[(size_t)(o0 + ty + 8*k) * C_ + c0 + tx];   // t[o_local][c_local]
    __syncthreads();
#pragma unroll
    for (int k = 0; k < 4; k++)
        g_wt[blockIdx.z][(size_t)(c0 + ty + 8*k) * C_ + o0 + tx] = __float2bfloat16(t[tx][ty + 8*k]);
}

// ---------------------------------------------------------------------------
// K1: groupnorm statistics. grid (B*G = 128), block 256
// ---------------------------------------------------------------------------
__global__ void gn_stats(const float* __restrict__ x) {
    int bg = blockIdx.x;
    int b = bg / G_, g = bg % G_;
    const float* base = x + (size_t)b * C_ * N_ + (size_t)g * CPG * N_;
    float s = 0.f, ss = 0.f;
    for (int i = threadIdx.x; i < CPG * N_; i += blockDim.x) {
        float v = base[i];
        s += v; ss += v * v;
    }
#pragma unroll
    for (int o = 16; o; o >>= 1) {
        s  += __shfl_xor_sync(0xffffffffu, s,  o);
        ss += __shfl_xor_sync(0xffffffffu, ss, o);
    }
    __shared__ float rs[8], rss[8];
    int w = threadIdx.x >> 5, lane = threadIdx.x & 31;
    if (lane == 0) { rs[w] = s; rss[w] = ss; }
    __syncthreads();
    if (w == 0) {
        s  = (lane < 8) ? rs[lane]  : 0.f;
        ss = (lane < 8) ? rss[lane] : 0.f;
#pragma unroll
        for (int o = 4; o; o >>= 1) {
            s  += __shfl_xor_sync(0xffffffffu, s,  o);
            ss += __shfl_xor_sync(0xffffffffu, ss, o);
        }
        if (lane == 0) {
            const float M = (float)(CPG * N_);
            float m = s / M;
            float var = ss / M - m * m;
            g_mean[bg] = m;
            g_rstd[bg] = rsqrtf(var + 1e-6f);
        }
    }
}

// ---------------------------------------------------------------------------
// K2: apply groupnorm + transpose to token-major bf16.  grid (128,16,4), block (32,8)
// ---------------------------------------------------------------------------
__global__ void gn_apply(const float* __restrict__ x, const float* __restrict__ gs,
                         const float* __restrict__ gb) {
    __shared__ float t[32][33];
    int b = blockIdx.z;
    int i0 = blockIdx.x * 32, c0 = blockIdx.y * 32;
    int tx = threadIdx.x, ty = threadIdx.y;
    const float* xb = x + (size_t)b * C_ * N_;
#pragma unroll
    for (int k = 0; k < 4; k++)
        t[ty + 8*k][tx] = xb[(size_t)(c0 + ty + 8*k) * N_ + i0 + tx];   // t[c_local][i_local]
    __syncthreads();
#pragma unroll
    for (int k = 0; k < 4; k++) {
        int c = c0 + tx;
        int i = i0 + ty + 8*k;
        int bg = b * G_ + c / CPG;
        float m = g_mean[bg], r = g_rstd[bg];
        float val = (t[tx][ty + 8*k] - m) * r * gs[c] + gb[c];
        g_hn[((size_t)b * N_ + i) * C_ + c] = __float2bfloat16(val);
    }
}

// ---------------------------------------------------------------------------
// Pipelined GEMM engine: BM=128, BN=128, BK=64, 2-stage cp.async,
// 8 warps in 2x4 grid, warp tile 64x32 (m16n8k16).
//   C[i][o] = sum_c A[i][c] * Wt[c][o]
// smem layout: A stages [2][128][72] bf16, B stages [2][64][136] bf16
// ---------------------------------------------------------------------------
#define GA_ST 18432          // 128*72*2
#define GB_ST 17408          // 64*136*2
#define GB_OFF (2 * GA_ST)   // 36864
#define GEMM_SMEM_BYTES (GB_OFF + 2 * GB_ST)   // 71680

#define GEMM_LOAD_A(st, kb) do {                                             \
    _Pragma("unroll")                                                        \
    for (int t = 0; t < 4; t++) {                                            \
        int idx = tid + 256 * t;                                             \
        int r = idx >> 3, c = idx & 7;                                       \
        cpa16(smA + (st) * GA_ST + (uint32_t)(r * 72 + c * 8) * 2,           \
              A + (size_t)r * C_ + (kb) * 64 + c * 8);                       \
    } } while (0)

#define GEMM_LOAD_B(st, kb) do {                                             \
    _Pragma("unroll")                                                        \
    for (int t = 0; t < 4; t++) {                                            \
        int idx = tid + 256 * t;                                             \
        int r = idx >> 4, c = idx & 15;                                      \
        cpa16(smB + (st) * GB_ST + (uint32_t)(r * 136 + c * 8) * 2,          \
              Bw + (size_t)((kb) * 64 + r) * C_ + c * 8);                    \
    } } while (0)

#define GEMM_COMPUTE(st) do {                                                \
    uint32_t aA = smA + (st) * GA_ST + aAoff;                                \
    uint32_t aB = smB + (st) * GB_ST + aBoff;                                \
    _Pragma("unroll")                                                        \
    for (int ks = 0; ks < 4; ks++) {                                         \
        uint32_t af[4][4];                                                   \
        _Pragma("unroll")                                                    \
        for (int mb = 0; mb < 4; mb++)                                       \
            ldsm4(aA + mb * 2304 + ks * 32, af[mb]);                         \
        _Pragma("unroll")                                                    \
        for (int nb = 0; nb < 2; nb++) {                                     \
            uint32_t bfr[4];                                                 \
            ldsm4t(aB + ks * 4352 + nb * 32, bfr);                           \
            _Pragma("unroll")                                                \
            for (int mb = 0; mb < 4; mb++) {                                 \
                mma16816(acc[mb][nb * 2],     af[mb], bfr[0], bfr[1]);       \
                mma16816(acc[mb][nb * 2 + 1], af[mb], bfr[2], bfr[3]);       \
            }                                                                \
        }                                                                    \
    } } while (0)

#define GEMM_MAINLOOP() do {                                                 \
    GEMM_LOAD_A(0, 0); GEMM_LOAD_B(0, 0); CP_COMMIT();                       \
    for (int kb = 0; kb < 8; kb++) {                                         \
        int st = kb & 1;                                                     \
        if (kb < 7) {                                                        \
            GEMM_LOAD_A(st ^ 1, kb + 1); GEMM_LOAD_B(st ^ 1, kb + 1);        \
            CP_COMMIT(); CP_WAIT1();                                         \
        } else { CP_WAIT0(); }                                               \
        __syncthreads();                                                     \
        GEMM_COMPUTE(st);                                                    \
        __syncthreads();                                                     \
    } } while (0)

// K3: QKV projection -> bf16 [b][i][o].  grid (32, 4, 12), block 256
__global__ __launch_bounds__(256, 2) void gemm_qkv(const float* __restrict__ bq,
                                                   const float* __restrict__ bk,
                                                   const float* __restrict__ bv) {
    extern __shared__ char smraw[];
    const uint32_t smA = smem_u32(smraw);
    const uint32_t smB = smA + GB_OFF;

    int bz = blockIdx.z;
    int b = bz / 3, which = bz % 3;
    const bf16* A  = g_hn + ((size_t)b * N_ + blockIdx.x * 128) * C_;
    const bf16* Bw = g_wt[which] + blockIdx.y * 128;
    bf16* outp = (which == 0 ? g_q : which == 1 ? g_k : g_v) + (size_t)b * N_ * C_;
    const float* bias = (which == 0 ? bq : which == 1 ? bk : bv);

    int i0 = blockIdx.x * 128, o0 = blockIdx.y * 128;
    int tid = threadIdx.x, lane = tid & 31, warp = tid >> 5;
    int wr = warp >> 2, wcn = warp & 3;
    int g = lane >> 2, q4 = lane & 3;

    const uint32_t aAoff = ((uint32_t)(wr * 64 + (lane & 15)) * 72 + (lane >> 4) * 8) * 2;
    const uint32_t aBoff = ((uint32_t)((lane & 7) + ((lane >> 3) & 1) * 8) * 136
                            + wcn * 32 + (lane >> 4) * 8) * 2;

    float acc[4][4][4];
#pragma unroll
    for (int mb = 0; mb < 4; mb++)
#pragma unroll
        for (int nb = 0; nb < 4; nb++)
#pragma unroll
            for (int e = 0; e < 4; e++) acc[mb][nb][e] = 0.f;

    GEMM_MAINLOOP();

    // epilogue: +bias, bf16, stage via smem (stride 136), coalesced store
    bf16* sO = (bf16*)smraw;
#pragma unroll
    for (int mb = 0; mb < 4; mb++) {
        int row = wr * 64 + mb * 16 + g;
#pragma unroll
        for (int nb = 0; nb < 4; nb++) {
            int col = wcn * 32 + nb * 8 + 2 * q4;
            float b0 = bias[o0 + col], b1 = bias[o0 + col + 1];
            __nv_bfloat162 v1 = __floats2bfloat162_rn(acc[mb][nb][0] + b0, acc[mb][nb][1] + b1);
            __nv_bfloat162 v2 = __floats2bfloat162_rn(acc[mb][nb][2] + b0, acc[mb][nb][3] + b1);
            *(uint32_t*)(sO + (size_t)row * 136 + col)       = *(uint32_t*)&v1;
            *(uint32_t*)(sO + (size_t)(row + 8) * 136 + col) = *(uint32_t*)&v2;
        }
    }
    __syncthreads();
#pragma unroll
    for (int t = 0; t < 8; t++) {
        int idx = tid + 256 * t;
        int r = idx >> 4, c = idx & 15;
        *(uint4*)(outp + (size_t)(i0 + r) * C_ + o0 + c * 8) =
            *(const uint4*)(sO + (size_t)r * 136 + c * 8);
    }
}

// K6: proj GEMM + bias + residual, transposed store into d_out. grid (32, 4, 4)
__global__ __launch_bounds__(256, 2) void gemm_proj(const float* __restrict__ x,
                                                    const float* __restrict__ bp,
                                                    float* __restrict__ out) {
    extern __shared__ char smraw[];
    const uint32_t smA = smem_u32(smraw);
    const uint32_t smB = smA + GB_OFF;

    int b = blockIdx.z;
    const bf16* A  = g_hn + ((size_t)b * N_ + blockIdx.x * 128) * C_;  // g_hn holds normalized attn out
    const bf16* Bw = g_wt[3] + blockIdx.y * 128;

    int i0 = blockIdx.x * 128, o0 = blockIdx.y * 128;
    int tid = threadIdx.x, lane = tid & 31, warp = tid >> 5;
    int wr = warp >> 2, wcn = warp & 3;
    int g = lane >> 2, q4 = lane & 3;

    const uint32_t aAoff = ((uint32_t)(wr * 64 + (lane & 15)) * 72 + (lane >> 4) * 8) * 2;
    const uint32_t aBoff = ((uint32_t)((lane & 7) + ((lane >> 3) & 1) * 8) * 136
                            + wcn * 32 + (lane >> 4) * 8) * 2;

    float acc[4][4][4];
#pragma unroll
    for (int mb = 0; mb < 4; mb++)
#pragma unroll
        for (int nb = 0; nb < 4; nb++)
#pragma unroll
            for (int e = 0; e < 4; e++) acc[mb][nb][e] = 0.f;

    GEMM_MAINLOOP();

    // epilogue: stage fp32 via smem (stride 129), then +bias +residual, transposed store
    float* sO = (float*)smraw;
#pragma unroll
    for (int mb = 0; mb < 4; mb++) {
        int row = wr * 64 + mb * 16 + g;
#pragma unroll
        for (int nb = 0; nb < 4; nb++) {
            int col = wcn * 32 + nb * 8 + 2 * q4;
            sO[(size_t)row * 129 + col]           = acc[mb][nb][0];
            sO[(size_t)row * 129 + col + 1]       = acc[mb][nb][1];
            sO[(size_t)(row + 8) * 129 + col]     = acc[mb][nb][2];
            sO[(size_t)(row + 8) * 129 + col + 1] = acc[mb][nb][3];
        }
    }
    __syncthreads();
    const float* xb   = x   + (size_t)b * C_ * N_;
    float*       outb = out + (size_t)b * C_ * N_;
#pragma unroll 4
    for (int t = 0; t < 64; t++) {
        int idx = tid + 256 * t;
        int ol = idx >> 7, il = idx & 127;
        float v = sO[(size_t)il * 129 + ol] + bp[o0 + ol]
                + xb[(size_t)(o0 + ol) * N_ + i0 + il];
        outb[(size_t)(o0 + ol) * N_ + i0 + il] = v;
    }
}

// ---------------------------------------------------------------------------
// K4: flash attention, raw mma.m16n8k16, register softmax (no-max, exp direct).
//   grid (64, 4), 256 threads, 1 CTA/SM.
// ---------------------------------------------------------------------------
#define QS 520   // bf16 row stride for Q/K/V tiles (512 + 8 pad)
#define PS 72    // bf16 row stride for P tile
#define OFF_K   (64 * QS * 2)
#define OFF_V   (2 * 64 * QS * 2)
#define OFF_P   (3 * 64 * QS * 2)
#define OFF_L   (OFF_P + 64 * PS * 2)
#define OFF_LP  (OFF_L + 64 * 4)
#define FLASH_SMEM_BYTES (OFF_LP + 128 * 4)   // 209664

__global__ __launch_bounds__(256, 1) void flash_kernel() {
    extern __shared__ char sm[];
    uint32_t*  sPw   = (uint32_t*)(sm + OFF_P);
    float*     sl    = (float*)(sm + OFF_L);
    float*     sPart = (float*)(sm + OFF_LP);

    const int b  = blockIdx.y;
    const int i0 = blockIdx.x * 64;
    const bf16* qg = g_q + ((size_t)b * N_ + i0) * C_;
    const bf16* kg = g_k + (size_t)b * N_ * C_;
    const bf16* vg = g_v + (size_t)b * N_ * C_;

    const int tid = threadIdx.x, lane = tid & 31, warp = tid >> 5;
    const int g = lane >> 2, q4 = lane & 3;

    const uint32_t sQa = smem_u32(sm);
    const uint32_t sKa = sQa + OFF_K;
    const uint32_t sVa = sQa + OFF_V;
    const uint32_t sPa = sQa + OFF_P;

#pragma unroll
    for (int t = 0; t < 16; t++) {
        int idx = tid + 256 * t;
        int r = idx >> 6, c8 = idx & 63;
        cpa16(sQa + (r * QS + c8 * 8) * 2, qg + (size_t)r * C_ + c8 * 8);
    }
    CP_COMMIT();
#pragma unroll
    for (int t = 0; t < 16; t++) {
        int idx = tid + 256 * t;
        int r = idx >> 6, c8 = idx & 63;
        cpa16(sKa + (r * QS + c8 * 8) * 2, kg + (size_t)r * C_ + c8 * 8);
    }
    CP_COMMIT();
    if (tid < 64) sl[tid] = 0.f;

    float oacc[4][8][4];
#pragma unroll
    for (int mb = 0; mb < 4; mb++)
#pragma unroll
        for (int nb = 0; nb < 8; nb++)
#pragma unroll
            for (int e = 0; e < 4; e++) oacc[mb][nb][e] = 0.f;

    const int sm0 = (warp >> 1) * 16;
    const int sn0 = (warp & 1) * 32;
    const int wc  = warp & 1;
    const int cw = warp * 64;

    const uint32_t aQ = sQa + ((sm0 + (lane & 15)) * QS + (lane >> 4) * 8) * 2;
    const uint32_t aK = sKa + ((sn0 + (lane & 7) + ((lane >> 4) << 3)) * QS
                               + ((lane >> 3) & 1) * 8) * 2;
    const uint32_t aP = sPa + (((lane & 15)) * PS + (lane >> 4) * 8) * 2;
    const uint32_t aV = sVa + (((lane & 7) + ((lane >> 3) & 1) * 8) * QS
                               + cw + (lane >> 4) * 8) * 2;

    const int pw1 = (sm0 + g) * (PS / 2) + (sn0 >> 1) + q4;
    const int pw2 = pw1 + 8 * (PS / 2);

    const float RS2 = RSCALE * 1.4426950408889634f;   // fold 1/sqrt(C) into exp2

    CP_WAIT0();
    __syncthreads();

    for (int jt = 0; jt < 64; jt++) {
        // prefetch V(jt)
#pragma unroll
        for (int t = 0; t < 16; t++) {
            int idx = tid + 256 * t;
            int r = idx >> 6, c8 = idx & 63;
            cpa16(sVa + (r * QS + c8 * 8) * 2,
                  vg + ((size_t)(jt * 64 + r)) * C_ + c8 * 8);
        }
        CP_COMMIT();

        // ---- S = Q K^T ----
        float sacc[4][4];
#pragma unroll
        for (int nb = 0; nb < 4; nb++)
#pragma unroll
            for (int e = 0; e < 4; e++) sacc[nb][e] = 0.f;

        uint32_t afr[2][4], bfr[2][8];
        ldsm4(aQ, afr[0]);
        ldsm4(aK, bfr[0]);
        ldsm4(aK + 16 * QS * 2, bfr[0] + 4);
#pragma unroll
        for (int ks = 0; ks < 32; ks++) {
            int cur = ks & 1, nxt = cur ^ 1;
            if (ks < 31) {
                uint32_t o = (uint32_t)(ks + 1) * 32;
                ldsm4(aQ + o, afr[nxt]);
                ldsm4(aK + o, bfr[nxt]);
                ldsm4(aK + o + 16 * QS * 2, bfr[nxt] + 4);
            }
            mma16816(sacc[0], afr[cur], bfr[cur][0], bfr[cur][1]);
            mma16816(sacc[1], afr[cur], bfr[cur][2], bfr[cur][3]);
            mma16816(sacc[2], afr[cur], bfr[cur][4], bfr[cur][5]);
            mma16816(sacc[3], afr[cur], bfr[cur][6], bfr[cur][7]);
        }

        CP_WAIT0();   // V(jt) landed

        // ---- register softmax ----
        float l1 = 0.f, l2 = 0.f;
#pragma unroll
        for (int nb = 0; nb < 4; nb++) {
            float e0 = exp2f(sacc[nb][0] * RS2);
            float e1 = exp2f(sacc[nb][1] * RS2);
            float e2 = exp2f(sacc[nb][2] * RS2);
            float e3 = exp2f(sacc[nb][3] * RS2);
            l1 += e0 + e1; l2 += e2 + e3;
            __nv_bfloat162 p01 = __floats2bfloat162_rn(e0, e1);
            __nv_bfloat162 p23 = __floats2bfloat162_rn(e2, e3);
            sPw[pw1 + nb * 4] = *(uint32_t*)&p01;
            sPw[pw2 + nb * 4] = *(uint32_t*)&p23;
        }
        l1 += __shfl_xor_sync(0xffffffffu, l1, 1);
        l1 += __shfl_xor_sync(0xffffffffu, l1, 2);
        l2 += __shfl_xor_sync(0xffffffffu, l2, 1);
        l2 += __shfl_xor_sync(0xffffffffu, l2, 2);
        if (q4 == 0) {
            sPart[wc * 64 + sm0 + g]     = l1;
            sPart[wc * 64 + sm0 + g + 8] = l2;
        }
        __syncthreads();
        if (tid < 64) sl[tid] += sPart[tid] + sPart[64 + tid];

        // prefetch K(jt+1)
        if (jt < 63) {
#pragma unroll
            for (int t = 0; t < 16; t++) {
                int idx = tid + 256 * t;
                int r = idx >> 6, c8 = idx & 63;
                cpa16(sKa + (r * QS + c8 * 8) * 2,
                      kg + ((size_t)((jt + 1) * 64 + r)) * C_ + c8 * 8);
            }
        }
        CP_COMMIT();

        // ---- O += P @ V ----
#pragma unroll
        for (int ks = 0; ks < 4; ks++) {
            uint32_t pa[4][4];
#pragma unroll
            for (int mb = 0; mb < 4; mb++)
                ldsm4(aP + (uint32_t)(mb * 16 * PS * 2 + ks * 32), pa[mb]);
#pragma unroll
            for (int nb2 = 0; nb2 < 4; nb2++) {
                uint32_t vb[4];
                ldsm4t(aV + (uint32_t)(ks * 16 * QS * 2 + nb2 * 32), vb);
#pragma unroll
                for (int mb = 0; mb < 4; mb++) {
                    mma16816(oacc[mb][nb2 * 2],     pa[mb], vb[0], vb[1]);
                    mma16816(oacc[mb][nb2 * 2 + 1], pa[mb], vb[2], vb[3]);
                }
            }
        }

        CP_WAIT0();
        __syncthreads();
    }

    // ---- epilogue ----
    float inv1[4], inv2[4];
#pragma unroll
    for (int mb = 0; mb < 4; mb++) {
        inv1[mb] = 1.f / sl[mb * 16 + g];
        inv2[mb] = 1.f / sl[mb * 16 + g + 8];
    }
    bf16* og = g_hn + ((size_t)b * N_ + i0) * C_;
#pragma unroll
    for (int mb = 0; mb < 4; mb++) {
        int r1 = mb * 16 + g;
#pragma unroll
        for (int nb = 0; nb < 8; nb++) {
            int c = cw + nb * 8 + 2 * q4;
            __nv_bfloat162 v1 = __floats2bfloat162_rn(oacc[mb][nb][0] * inv1[mb],
                                                      oacc[mb][nb][1] * inv1[mb]);
            __nv_bfloat162 v2 = __floats2bfloat162_rn(oacc[mb][nb][2] * inv2[mb],
                                                      oacc[mb][nb][3] * inv2[mb]);
            *(uint32_t*)(og + (size_t)r1 * C_ + c)       = *(uint32_t*)&v1;
            *(uint32_t*)(og + (size_t)(r1 + 8) * C_ + c) = *(uint32_t*)&v2;
        }
    }
}

// ---------------------------------------------------------------------------
// Launch
// ---------------------------------------------------------------------------
extern "C" void kernel_launch(void* const* d_in, const int* in_sizes, int n_in,
                              void* d_out, int out_size) {
    const float* x  = (const float*)d_in[0];
    const float* gs = (const float*)d_in[1];
    const float* gb = (const float*)d_in[2];
    const float* wq = (const float*)d_in[3];
    const float* bq = (const float*)d_in[4];
    const float* wk = (const float*)d_in[5];
    const float* bk = (const float*)d_in[6];
    const float* wv = (const float*)d_in[7];
    const float* bv = (const float*)d_in[8];
    const float* wp = (const float*)d_in[9];
    const float* bp = (const float*)d_in[10];
    float* out = (float*)d_out;

    cudaFuncSetAttribute(flash_kernel, cudaFuncAttributeMaxDynamicSharedMemorySize,
                         FLASH_SMEM_BYTES);
    cudaFuncSetAttribute(gemm_qkv, cudaFuncAttributeMaxDynamicSharedMemorySize,
                         GEMM_SMEM_BYTES);
    cudaFuncSetAttribute(gemm_proj, cudaFuncAttributeMaxDynamicSharedMemorySize,
                         GEMM_SMEM_BYTES);

    prep_weights<<<dim3(16, 16, 4), dim3(32, 8)>>>(wq, wk, wv, wp);
    gn_stats<<<B_ * G_, 256>>>(x);
    gn_apply<<<dim3(N_ / 32, C_ / 32, B_), dim3(32, 8)>>>(x, gs, gb);
    gemm_qkv<<<dim3(N_ / 128, C_ / 128, B_ * 3), 256, GEMM_SMEM_BYTES>>>(bq, bk, bv);
    flash_kernel<<<dim3(N_ / 64, B_), 256, FLASH_SMEM_BYTES>>>();
    gemm_proj<<<dim3(N_ / 128, C_ / 128, B_), 256, GEMM_SMEM_BYTES>>>(x, bp, out);
}

// round 10
// speedup vs baseline: 1.8902x; 1.0011x over previous
#include <cuda_runtime.h>
#include <cuda_bf16.h>
#include <cstdint>

using bf16 = __nv_bfloat16;

#define B_  4
#define C_  512
#define N_  4096
#define G_  32
#define CPG 16           // channels per group = C_/G_

static __device__ __align__(16) bf16  g_hn[(size_t)B_*N_*C_];   // normed x, token-major [b][i][c]; reused for attn output
static __device__ __align__(16) bf16  g_q [(size_t)B_*N_*C_];   // [b][i][c]
static __device__ __align__(16) bf16  g_k [(size_t)B_*N_*C_];
static __device__ __align__(16) bf16  g_v [(size_t)B_*N_*C_];
static __device__ __align__(16) bf16  g_wt[4][C_*C_];           // transposed bf16 weights: Wt[c][o] = W[o][c]
static __device__ float g_mean[B_*G_];
static __device__ float g_rstd[B_*G_];

#define RSCALE 0.044194173824159216f   // 1/sqrt(512)

// ---------------------------------------------------------------------------
// common PTX helpers
// ---------------------------------------------------------------------------
__device__ __forceinline__ uint32_t smem_u32(const void* p) {
    return (uint32_t)__cvta_generic_to_shared(p);
}
__device__ __forceinline__ void cpa16(uint32_t dst, const void* src) {
    asm volatile("cp.async.cg.shared.global [%0], [%1], 16;\n" :: "r"(dst), "l"(src));
}
#define CP_COMMIT() asm volatile("cp.async.commit_group;\n")
#define CP_WAIT0()  asm volatile("cp.async.wait_group 0;\n")
#define CP_WAIT1()  asm volatile("cp.async.wait_group 1;\n")

__device__ __forceinline__ void ldsm4(uint32_t a, uint32_t* r) {
    asm volatile("ldmatrix.sync.aligned.m8n8.x4.shared.b16 {%0,%1,%2,%3}, [%4];\n"
        : "=r"(r[0]), "=r"(r[1]), "=r"(r[2]), "=r"(r[3]) : "r"(a));
}
__device__ __forceinline__ void ldsm4t(uint32_t a, uint32_t* r) {
    asm volatile("ldmatrix.sync.aligned.m8n8.x4.trans.shared.b16 {%0,%1,%2,%3}, [%4];\n"
        : "=r"(r[0]), "=r"(r[1]), "=r"(r[2]), "=r"(r[3]) : "r"(a));
}
__device__ __forceinline__ void mma16816(float* d, const uint32_t* a, uint32_t b0, uint32_t b1) {
    asm volatile("mma.sync.aligned.m16n8k16.row.col.f32.bf16.bf16.f32 "
        "{%0,%1,%2,%3}, {%4,%5,%6,%7}, {%8,%9}, {%0,%1,%2,%3};\n"
        : "+f"(d[0]), "+f"(d[1]), "+f"(d[2]), "+f"(d[3])
        : "r"(a[0]), "r"(a[1]), "r"(a[2]), "r"(a[3]), "r"(b0), "r"(b1));
}

// ---------------------------------------------------------------------------
// K0: weight transpose + bf16 convert.  grid (16,16,4), block (32,8)
// ---------------------------------------------------------------------------
__global__ void prep_weights(const float* __restrict__ wq, const float* __restrict__ wk,
                             const float* __restrict__ wv, const float* __restrict__ wp) {
    __shared__ float t[32][33];
    const float* Wsel[4] = {wq, wk, wv, wp};
    const float* src = Wsel[blockIdx.z];
    int o0 = blockIdx.x * 32, c0 = blockIdx.y * 32;
    int tx = threadIdx.x, ty = threadIdx.y;
#pragma unroll
    for (int k = 0; k < 4; k++)
        t[ty + 8*k][tx] = src[(size_t)(o0 + ty + 8*k) * C_ + c0 + tx];   // t[o_local][c_local]
    __syncthreads();
#pragma unroll
    for (int k = 0; k < 4; k++)
        g_wt[blockIdx.z][(size_t)(c0 + ty + 8*k) * C_ + o0 + tx] = __float2bfloat16(t[tx][ty + 8*k]);
}

// ---------------------------------------------------------------------------
// K1: groupnorm statistics. grid (B*G = 128), block 256
// ---------------------------------------------------------------------------
__global__ void gn_stats(const float* __restrict__ x) {
    int bg = blockIdx.x;
    int b = bg / G_, g = bg % G_;
    const float* base = x + (size_t)b * C_ * N_ + (size_t)g * CPG * N_;
    float s = 0.f, ss = 0.f;
    for (int i = threadIdx.x; i < CPG * N_; i += blockDim.x) {
        float v = base[i];
        s += v; ss += v * v;
    }
#pragma unroll
    for (int o = 16; o; o >>= 1) {
        s  += __shfl_xor_sync(0xffffffffu, s,  o);
        ss += __shfl_xor_sync(0xffffffffu, ss, o);
    }
    __shared__ float rs[8], rss[8];
    int w = threadIdx.x >> 5, lane = threadIdx.x & 31;
    if (lane == 0) { rs[w] = s; rss[w] = ss; }
    __syncthreads();
    if (w == 0) {
        s  = (lane < 8) ? rs[lane]  : 0.f;
        ss = (lane < 8) ? rss[lane] : 0.f;
#pragma unroll
        for (int o = 4; o; o >>= 1) {
            s  += __shfl_xor_sync(0xffffffffu, s,  o);
            ss += __shfl_xor_sync(0xffffffffu, ss, o);
        }
        if (lane == 0) {
            const float M = (float)(CPG * N_);
            float m = s / M;
            float var = ss / M - m * m;
            g_mean[bg] = m;
            g_rstd[bg] = rsqrtf(var + 1e-6f);
        }
    }
}

// ---------------------------------------------------------------------------
// K2: apply groupnorm + transpose to token-major bf16.  grid (128,16,4), block (32,8)
// ---------------------------------------------------------------------------
__global__ void gn_apply(const float* __restrict__ x, const float* __restrict__ gs,
                         const float* __restrict__ gb) {
    __shared__ float t[32][33];
    int b = blockIdx.z;
    int i0 = blockIdx.x * 32, c0 = blockIdx.y * 32;
    int tx = threadIdx.x, ty = threadIdx.y;
    const float* xb = x + (size_t)b * C_ * N_;
#pragma unroll
    for (int k = 0; k < 4; k++)
        t[ty + 8*k][tx] = xb[(size_t)(c0 + ty + 8*k) * N_ + i0 + tx];   // t[c_local][i_local]
    __syncthreads();
#pragma unroll
    for (int k = 0; k < 4; k++) {
        int c = c0 + tx;
        int i = i0 + ty + 8*k;
        int bg = b * G_ + c / CPG;
        float m = g_mean[bg], r = g_rstd[bg];
        float val = (t[tx][ty + 8*k] - m) * r * gs[c] + gb[c];
        g_hn[((size_t)b * N_ + i) * C_ + c] = __float2bfloat16(val);
    }
}

// ---------------------------------------------------------------------------
// Pipelined GEMM engine: BM=128, BN=128, BK=64, 2-stage cp.async,
// 8 warps in 2x4 grid, warp tile 64x32 (m16n8k16).
//   C[i][o] = sum_c A[i][c] * Wt[c][o]
// smem layout: A stages [2][128][72] bf16, B stages [2][64][136] bf16
// ---------------------------------------------------------------------------
#define GA_ST 18432          // 128*72*2
#define GB_ST 17408          // 64*136*2
#define GB_OFF (2 * GA_ST)   // 36864
#define GEMM_SMEM_BYTES (GB_OFF + 2 * GB_ST)   // 71680

#define GEMM_LOAD_A(st, kb) do {                                             \
    _Pragma("unroll")                                                        \
    for (int t = 0; t < 4; t++) {                                            \
        int idx = tid + 256 * t;                                             \
        int r = idx >> 3, c = idx & 7;                                       \
        cpa16(smA + (st) * GA_ST + (uint32_t)(r * 72 + c * 8) * 2,           \
              A + (size_t)r * C_ + (kb) * 64 + c * 8);                       \
    } } while (0)

#define GEMM_LOAD_B(st, kb) do {                                             \
    _Pragma("unroll")                                                        \
    for (int t = 0; t < 4; t++) {                                            \
        int idx = tid + 256 * t;                                             \
        int r = idx >> 4, c = idx & 15;                                      \
        cpa16(smB + (st) * GB_ST + (uint32_t)(r * 136 + c * 8) * 2,          \
              Bw + (size_t)((kb) * 64 + r) * C_ + c * 8);                    \
    } } while (0)

#define GEMM_COMPUTE(st) do {                                                \
    uint32_t aA = smA + (st) * GA_ST + aAoff;                                \
    uint32_t aB = smB + (st) * GB_ST + aBoff;                                \
    _Pragma("unroll")                                                        \
    for (int ks = 0; ks < 4; ks++) {                                         \
        uint32_t af[4][4];                                                   \
        _Pragma("unroll")                                                    \
        for (int mb = 0; mb < 4; mb++)                                       \
            ldsm4(aA + mb * 2304 + ks * 32, af[mb]);                         \
        _Pragma("unroll")                                                    \
        for (int nb = 0; nb < 2; nb++) {                                     \
            uint32_t bfr[4];                                                 \
            ldsm4t(aB + ks * 4352 + nb * 32, bfr);                           \
            _Pragma("unroll")                                                \
            for (int mb = 0; mb < 4; mb++) {                                 \
                mma16816(acc[mb][nb * 2],     af[mb], bfr[0], bfr[1]);       \
                mma16816(acc[mb][nb * 2 + 1], af[mb], bfr[2], bfr[3]);       \
            }                                                                \
        }                                                                    \
    } } while (0)

#define GEMM_MAINLOOP() do {                                                 \
    GEMM_LOAD_A(0, 0); GEMM_LOAD_B(0, 0); CP_COMMIT();                       \
    for (int kb = 0; kb < 8; kb++) {                                         \
        int st = kb & 1;                                                     \
        if (kb < 7) {                                                        \
            GEMM_LOAD_A(st ^ 1, kb + 1); GEMM_LOAD_B(st ^ 1, kb + 1);        \
            CP_COMMIT(); CP_WAIT1();                                         \
        } else { CP_WAIT0(); }                                               \
        __syncthreads();                                                     \
        GEMM_COMPUTE(st);                                                    \
        __syncthreads();                                                     \
    } } while (0)

// K3: QKV projection -> bf16 [b][i][o].  grid (32, 4, 12), block 256
__global__ __launch_bounds__(256, 2) void gemm_qkv(const float* __restrict__ bq,
                                                   const float* __restrict__ bk,
                                                   const float* __restrict__ bv) {
    extern __shared__ char smraw[];
    const uint32_t smA = smem_u32(smraw);
    const uint32_t smB = smA + GB_OFF;

    int bz = blockIdx.z;
    int b = bz / 3, which = bz % 3;
    const bf16* A  = g_hn + ((size_t)b * N_ + blockIdx.x * 128) * C_;
    const bf16* Bw = g_wt[which] + blockIdx.y * 128;
    bf16* outp = (which == 0 ? g_q : which == 1 ? g_k : g_v) + (size_t)b * N_ * C_;
    const float* bias = (which == 0 ? bq : which == 1 ? bk : bv);

    int i0 = blockIdx.x * 128, o0 = blockIdx.y * 128;
    int tid = threadIdx.x, lane = tid & 31, warp = tid >> 5;
    int wr = warp >> 2, wcn = warp & 3;
    int g = lane >> 2, q4 = lane & 3;

    const uint32_t aAoff = ((uint32_t)(wr * 64 + (lane & 15)) * 72 + (lane >> 4) * 8) * 2;
    const uint32_t aBoff = ((uint32_t)((lane & 7) + ((lane >> 3) & 1) * 8) * 136
                            + wcn * 32 + (lane >> 4) * 8) * 2;

    float acc[4][4][4];
#pragma unroll
    for (int mb = 0; mb < 4; mb++)
#pragma unroll
        for (int nb = 0; nb < 4; nb++)
#pragma unroll
            for (int e = 0; e < 4; e++) acc[mb][nb][e] = 0.f;

    GEMM_MAINLOOP();

    // epilogue: +bias, bf16, stage via smem (stride 136), coalesced store
    bf16* sO = (bf16*)smraw;
#pragma unroll
    for (int mb = 0; mb < 4; mb++) {
        int row = wr * 64 + mb * 16 + g;
#pragma unroll
        for (int nb = 0; nb < 4; nb++) {
            int col = wcn * 32 + nb * 8 + 2 * q4;
            float b0 = bias[o0 + col], b1 = bias[o0 + col + 1];
            __nv_bfloat162 v1 = __floats2bfloat162_rn(acc[mb][nb][0] + b0, acc[mb][nb][1] + b1);
            __nv_bfloat162 v2 = __floats2bfloat162_rn(acc[mb][nb][2] + b0, acc[mb][nb][3] + b1);
            *(uint32_t*)(sO + (size_t)row * 136 + col)       = *(uint32_t*)&v1;
            *(uint32_t*)(sO + (size_t)(row + 8) * 136 + col) = *(uint32_t*)&v2;
        }
    }
    __syncthreads();
#pragma unroll
    for (int t = 0; t < 8; t++) {
        int idx = tid + 256 * t;
        int r = idx >> 4, c = idx & 15;
        *(uint4*)(outp + (size_t)(i0 + r) * C_ + o0 + c * 8) =
            *(const uint4*)(sO + (size_t)r * 136 + c * 8);
    }
}

// K6: proj GEMM + bias + residual, transposed store into d_out. grid (32, 4, 4)
__global__ __launch_bounds__(256, 2) void gemm_proj(const float* __restrict__ x,
                                                    const float* __restrict__ bp,
                                                    float* __restrict__ out) {
    extern __shared__ char smraw[];
    const uint32_t smA = smem_u32(smraw);
    const uint32_t smB = smA + GB_OFF;

    int b = blockIdx.z;
    const bf16* A  = g_hn + ((size_t)b * N_ + blockIdx.x * 128) * C_;  // g_hn holds normalized attn out
    const bf16* Bw = g_wt[3] + blockIdx.y * 128;

    int i0 = blockIdx.x * 128, o0 = blockIdx.y * 128;
    int tid = threadIdx.x, lane = tid & 31, warp = tid >> 5;
    int wr = warp >> 2, wcn = warp & 3;
    int g = lane >> 2, q4 = lane & 3;

    const uint32_t aAoff = ((uint32_t)(wr * 64 + (lane & 15)) * 72 + (lane >> 4) * 8) * 2;
    const uint32_t aBoff = ((uint32_t)((lane & 7) + ((lane >> 3) & 1) * 8) * 136
                            + wcn * 32 + (lane >> 4) * 8) * 2;

    float acc[4][4][4];
#pragma unroll
    for (int mb = 0; mb < 4; mb++)
#pragma unroll
        for (int nb = 0; nb < 4; nb++)
#pragma unroll
            for (int e = 0; e < 4; e++) acc[mb][nb][e] = 0.f;

    GEMM_MAINLOOP();

    // epilogue: stage fp32 via smem (stride 129), then +bias +residual, transposed store
    float* sO = (float*)smraw;
#pragma unroll
    for (int mb = 0; mb < 4; mb++) {
        int row = wr * 64 + mb * 16 + g;
#pragma unroll
        for (int nb = 0; nb < 4; nb++) {
            int col = wcn * 32 + nb * 8 + 2 * q4;
            sO[(size_t)row * 129 + col]           = acc[mb][nb][0];
            sO[(size_t)row * 129 + col + 1]       = acc[mb][nb][1];
            sO[(size_t)(row + 8) * 129 + col]     = acc[mb][nb][2];
            sO[(size_t)(row + 8) * 129 + col + 1] = acc[mb][nb][3];
        }
    }
    __syncthreads();
    const float* xb   = x   + (size_t)b * C_ * N_;
    float*       outb = out + (size_t)b * C_ * N_;
#pragma unroll 4
    for (int t = 0; t < 64; t++) {
        int idx = tid + 256 * t;
        int ol = idx >> 7, il = idx & 127;
        float v = sO[(size_t)il * 129 + ol] + bp[o0 + ol]
                + xb[(size_t)(o0 + ol) * N_ + i0 + il];
        outb[(size_t)(o0 + ol) * N_ + i0 + il] = v;
    }
}

// ---------------------------------------------------------------------------
// K4: flash attention, raw mma.m16n8k16, register softmax (no-max, exp direct).
//   grid (64, 4), 256 threads, 1 CTA/SM.
// ---------------------------------------------------------------------------
#define QS 520   // bf16 row stride for Q/K/V tiles (512 + 8 pad)
#define PS 72    // bf16 row stride for P tile
#define OFF_K   (64 * QS * 2)
#define OFF_V   (2 * 64 * QS * 2)
#define OFF_P   (3 * 64 * QS * 2)
#define OFF_L   (OFF_P + 64 * PS * 2)
#define OFF_LP  (OFF_L + 64 * 4)
#define FLASH_SMEM_BYTES (OFF_LP + 128 * 4)   // 209664

__global__ __launch_bounds__(256, 1) void flash_kernel() {
    extern __shared__ char sm[];
    uint32_t*  sPw   = (uint32_t*)(sm + OFF_P);
    float*     sl    = (float*)(sm + OFF_L);
    float*     sPart = (float*)(sm + OFF_LP);

    const int b  = blockIdx.y;
    const int i0 = blockIdx.x * 64;
    const bf16* qg = g_q + ((size_t)b * N_ + i0) * C_;
    const bf16* kg = g_k + (size_t)b * N_ * C_;
    const bf16* vg = g_v + (size_t)b * N_ * C_;

    const int tid = threadIdx.x, lane = tid & 31, warp = tid >> 5;
    const int g = lane >> 2, q4 = lane & 3;

    const uint32_t sQa = smem_u32(sm);
    const uint32_t sKa = sQa + OFF_K;
    const uint32_t sVa = sQa + OFF_V;
    const uint32_t sPa = sQa + OFF_P;

#pragma unroll
    for (int t = 0; t < 16; t++) {
        int idx = tid + 256 * t;
        int r = idx >> 6, c8 = idx & 63;
        cpa16(sQa + (r * QS + c8 * 8) * 2, qg + (size_t)r * C_ + c8 * 8);
    }
    CP_COMMIT();
#pragma unroll
    for (int t = 0; t < 16; t++) {
        int idx = tid + 256 * t;
        int r = idx >> 6, c8 = idx & 63;
        cpa16(sKa + (r * QS + c8 * 8) * 2, kg + (size_t)r * C_ + c8 * 8);
    }
    CP_COMMIT();
    if (tid < 64) sl[tid] = 0.f;

    float oacc[4][8][4];
#pragma unroll
    for (int mb = 0; mb < 4; mb++)
#pragma unroll
        for (int nb = 0; nb < 8; nb++)
#pragma unroll
            for (int e = 0; e < 4; e++) oacc[mb][nb][e] = 0.f;

    const int sm0 = (warp >> 1) * 16;
    const int sn0 = (warp & 1) * 32;
    const int wc  = warp & 1;
    const int cw = warp * 64;

    const uint32_t aQ = sQa + ((sm0 + (lane & 15)) * QS + (lane >> 4) * 8) * 2;
    const uint32_t aK = sKa + ((sn0 + (lane & 7) + ((lane >> 4) << 3)) * QS
                               + ((lane >> 3) & 1) * 8) * 2;
    const uint32_t aP = sPa + (((lane & 15)) * PS + (lane >> 4) * 8) * 2;
    const uint32_t aV = sVa + (((lane & 7) + ((lane >> 3) & 1) * 8) * QS
                               + cw + (lane >> 4) * 8) * 2;

    const int pw1 = (sm0 + g) * (PS / 2) + (sn0 >> 1) + q4;
    const int pw2 = pw1 + 8 * (PS / 2);

    const float RS2 = RSCALE * 1.4426950408889634f;   // fold 1/sqrt(C) into exp2

    CP_WAIT0();
    __syncthreads();

    for (int jt = 0; jt < 64; jt++) {
        // prefetch V(jt)
#pragma unroll
        for (int t = 0; t < 16; t++) {
            int idx = tid + 256 * t;
            int r = idx >> 6, c8 = idx & 63;
            cpa16(sVa + (r * QS + c8 * 8) * 2,
                  vg + ((size_t)(jt * 64 + r)) * C_ + c8 * 8);
        }
        CP_COMMIT();

        // ---- S = Q K^T ----
        float sacc[4][4];
#pragma unroll
        for (int nb = 0; nb < 4; nb++)
#pragma unroll
            for (int e = 0; e < 4; e++) sacc[nb][e] = 0.f;

        uint32_t afr[2][4], bfr[2][8];
        ldsm4(aQ, afr[0]);
        ldsm4(aK, bfr[0]);
        ldsm4(aK + 16 * QS * 2, bfr[0] + 4);
#pragma unroll
        for (int ks = 0; ks < 32; ks++) {
            int cur = ks & 1, nxt = cur ^ 1;
            if (ks < 31) {
                uint32_t o = (uint32_t)(ks + 1) * 32;
                ldsm4(aQ + o, afr[nxt]);
                ldsm4(aK + o, bfr[nxt]);
                ldsm4(aK + o + 16 * QS * 2, bfr[nxt] + 4);
            }
            mma16816(sacc[0], afr[cur], bfr[cur][0], bfr[cur][1]);
            mma16816(sacc[1], afr[cur], bfr[cur][2], bfr[cur][3]);
            mma16816(sacc[2], afr[cur], bfr[cur][4], bfr[cur][5]);
            mma16816(sacc[3], afr[cur], bfr[cur][6], bfr[cur][7]);
        }

        CP_WAIT0();   // V(jt) landed

        // ---- register softmax ----
        float l1 = 0.f, l2 = 0.f;
#pragma unroll
        for (int nb = 0; nb < 4; nb++) {
            float e0 = exp2f(sacc[nb][0] * RS2);
            float e1 = exp2f(sacc[nb][1] * RS2);
            float e2 = exp2f(sacc[nb][2] * RS2);
            float e3 = exp2f(sacc[nb][3] * RS2);
            l1 += e0 + e1; l2 += e2 + e3;
            __nv_bfloat162 p01 = __floats2bfloat162_rn(e0, e1);
            __nv_bfloat162 p23 = __floats2bfloat162_rn(e2, e3);
            sPw[pw1 + nb * 4] = *(uint32_t*)&p01;
            sPw[pw2 + nb * 4] = *(uint32_t*)&p23;
        }
        l1 += __shfl_xor_sync(0xffffffffu, l1, 1);
        l1 += __shfl_xor_sync(0xffffffffu, l1, 2);
        l2 += __shfl_xor_sync(0xffffffffu, l2, 1);
        l2 += __shfl_xor_sync(0xffffffffu, l2, 2);
        if (q4 == 0) {
            sPart[wc * 64 + sm0 + g]     = l1;
            sPart[wc * 64 + sm0 + g + 8] = l2;
        }
        __syncthreads();
        if (tid < 64) sl[tid] += sPart[tid] + sPart[64 + tid];

        // prefetch K(jt+1)
        if (jt < 63) {
#pragma unroll
            for (int t = 0; t < 16; t++) {
                int idx = tid + 256 * t;
                int r = idx >> 6, c8 = idx & 63;
                cpa16(sKa + (r * QS + c8 * 8) * 2,
                      kg + ((size_t)((jt + 1) * 64 + r)) * C_ + c8 * 8);
            }
        }
        CP_COMMIT();

        // ---- O += P @ V ----
#pragma unroll
        for (int ks = 0; ks < 4; ks++) {
            uint32_t pa[4][4];
#pragma unroll
            for (int mb = 0; mb < 4; mb++)
                ldsm4(aP + (uint32_t)(mb * 16 * PS * 2 + ks * 32), pa[mb]);
#pragma unroll
            for (int nb2 = 0; nb2 < 4; nb2++) {
                uint32_t vb[4];
                ldsm4t(aV + (uint32_t)(ks * 16 * QS * 2 + nb2 * 32), vb);
#pragma unroll
                for (int mb = 0; mb < 4; mb++) {
                    mma16816(oacc[mb][nb2 * 2],     pa[mb], vb[0], vb[1]);
                    mma16816(oacc[mb][nb2 * 2 + 1], pa[mb], vb[2], vb[3]);
                }
            }
        }

        CP_WAIT0();
        __syncthreads();
    }

    // ---- epilogue ----
    float inv1[4], inv2[4];
#pragma unroll
    for (int mb = 0; mb < 4; mb++) {
        inv1[mb] = 1.f / sl[mb * 16 + g];
        inv2[mb] = 1.f / sl[mb * 16 + g + 8];
    }
    bf16* og = g_hn + ((size_t)b * N_ + i0) * C_;
#pragma unroll
    for (int mb = 0; mb < 4; mb++) {
        int r1 = mb * 16 + g;
#pragma unroll
        for (int nb = 0; nb < 8; nb++) {
            int c = cw + nb * 8 + 2 * q4;
            __nv_bfloat162 v1 = __floats2bfloat162_rn(oacc[mb][nb][0] * inv1[mb],
                                                      oacc[mb][nb][1] * inv1[mb]);
            __nv_bfloat162 v2 = __floats2bfloat162_rn(oacc[mb][nb][2] * inv2[mb],
                                                      oacc[mb][nb][3] * inv2[mb]);
            *(uint32_t*)(og + (size_t)r1 * C_ + c)       = *(uint32_t*)&v1;
            *(uint32_t*)(og + (size_t)(r1 + 8) * C_ + c) = *(uint32_t*)&v2;
        }
    }
}

// ---------------------------------------------------------------------------
// Launch
// ---------------------------------------------------------------------------
extern "C" void kernel_launch(void* const* d_in, const int* in_sizes, int n_in,
                              void* d_out, int out_size) {
    const float* x  = (const float*)d_in[0];
    const float* gs = (const float*)d_in[1];
    const float* gb = (const float*)d_in[2];
    const float* wq = (const float*)d_in[3];
    const float* bq = (const float*)d_in[4];
    const float* wk = (const float*)d_in[5];
    const float* bk = (const float*)d_in[6];
    const float* wv = (const float*)d_in[7];
    const float* bv = (const float*)d_in[8];
    const float* wp = (const float*)d_in[9];
    const float* bp = (const float*)d_in[10];
    float* out = (float*)d_out;

    cudaFuncSetAttribute(flash_kernel, cudaFuncAttributeMaxDynamicSharedMemorySize,
                         FLASH_SMEM_BYTES);
    cudaFuncSetAttribute(gemm_qkv, cudaFuncAttributeMaxDynamicSharedMemorySize,
                         GEMM_SMEM_BYTES);
    cudaFuncSetAttribute(gemm_proj, cudaFuncAttributeMaxDynamicSharedMemorySize,
                         GEMM_SMEM_BYTES);

    prep_weights<<<dim3(16, 16, 4), dim3(32, 8)>>>(wq, wk, wv, wp);
    gn_stats<<<B_ * G_, 256>>>(x);
    gn_apply<<<dim3(N_ / 32, C_ / 32, B_), dim3(32, 8)>>>(x, gs, gb);
    gemm_qkv<<<dim3(N_ / 128, C_ / 128, B_ * 3), 256, GEMM_SMEM_BYTES>>>(bq, bk, bv);
    flash_kernel<<<dim3(N_ / 64, B_), 256, FLASH_SMEM_BYTES>>>();
    gemm_proj<<<dim3(N_ / 128, C_ / 128, B_), 256, GEMM_SMEM_BYTES>>>(x, bp, out);
}